// round 2
// baseline (speedup 1.0000x reference)
#include <cuda_runtime.h>
#include <math.h>

// Problem constants
#define BB   16
#define SS   512
#define SS0  511
#define DD   512
#define HGH  256
#define HEH  256
#define TT   128
#define MM   32
#define NN   (BB*SS)   // 8192

// ---------------- device scratch (no runtime allocation allowed) ----------------
__device__ float  d_X   [NN*DD];     // input with sentinel row, (N, D)
__device__ float  d_XW  [NN*HGH];    // input projection for current scan layer
__device__ float  d_H0  [NN*HGH];    // layer-0 hidden states
__device__ float  d_GS  [NN*HGH];    // masked layer-1 hidden states (gs)
__device__ float  d_h0a [NN*HEH];
__device__ float  d_h0b [NN*HEH];
__device__ float  d_h1a [NN*HEH];
__device__ float  d_h1b [NN*HEH];
__device__ float  d_zero[NN*HEH];    // zeros (h1 init)
__device__ float  d_pa  [NN];
__device__ float  d_pb  [NN];
__device__ float  d_ones[NN];        // p init
__device__ float  d_probs[MM*NN];

__device__ float  d_WT_ih0g[DD*HGH];   // g_Wih0^T  (D x HG)
__device__ float  d_WT_ih1g[HGH*HGH];  // g_Wih1^T
__device__ float4 d_Wp0[(HGH/4)*HGH];  // packed g_Whh0 for scan
__device__ float4 d_Wp1[(HGH/4)*HGH];  // packed g_Whh1 for scan
__device__ float  d_WT_hh0e[HEH*HEH];  // e_Whh0^T
__device__ float  d_WT_ih1e[HEH*HEH];  // e_Wih1^T
__device__ float  d_WT_hh1e[HEH*HEH];  // e_Whh1^T
__device__ float  d_WT_head[HGH*TT];   // head_W^T (HG x T)
__device__ float  d_WT_dep [HGH*TT];   // dep_W^T

// ---------------- small prep kernels ----------------

// Build X: row n=(b*S+s): s==0 -> sentinel, else input[b, s-1, :]. float4 granularity.
__global__ void build_x_kernel(const float* __restrict__ input,
                               const float* __restrict__ sent,
                               float* __restrict__ X)
{
    int idx = blockIdx.x * blockDim.x + threadIdx.x;   // over NN*DD/4 float4s
    int n  = idx >> 7;          // DD/4 = 128 float4 per row
    int k4 = idx & 127;
    int b = n >> 9, s = n & 511;
    float4 v;
    if (s == 0) v = ((const float4*)sent)[k4];
    else        v = ((const float4*)input)[(size_t)((b*SS0 + s - 1) << 7) + k4];
    ((float4*)X)[idx] = v;
}

__global__ void init_ones_kernel(float* __restrict__ ones)
{
    int i = blockIdx.x * blockDim.x + threadIdx.x;
    if (i < NN) ones[i] = 1.0f;
}

// Generic transpose: in (R x C) -> out (C x R)
__global__ void transpose_kernel(const float* __restrict__ in, float* __restrict__ out,
                                 int R, int C)
{
    __shared__ float tile[32][33];
    int c0 = blockIdx.x * 32, r0 = blockIdx.y * 32;
    int x = threadIdx.x, y = threadIdx.y;
    #pragma unroll
    for (int dy = 0; dy < 32; dy += 8) {
        int r = r0 + y + dy, c = c0 + x;
        if (r < R && c < C) tile[y + dy][x] = in[(size_t)r * C + c];
    }
    __syncthreads();
    #pragma unroll
    for (int dy = 0; dy < 32; dy += 8) {
        int r = r0 + x, c = c0 + y + dy;
        if (r < R && c < C) out[(size_t)c * R + r] = tile[x][y + dy];
    }
}

// Pack Whh (HG x HG, row major) into Wp[k4*HG + j] = {W[j][4k4..4k4+3]}
__global__ void pack_whh_kernel(const float* __restrict__ W, float4* __restrict__ Wp)
{
    int idx = blockIdx.x * blockDim.x + threadIdx.x;   // 64*256
    int k4 = idx >> 8, j = idx & 255;
    const float* src = W + (size_t)j * HGH + (k4 << 2);
    Wp[idx] = make_float4(src[0], src[1], src[2], src[3]);
}

// ---------------- g-RNN recurrence: one CTA per batch element ----------------
__global__ void __launch_bounds__(256) scan_g_kernel(const float* __restrict__ XW,
                                                     const float4* __restrict__ Wp,
                                                     float* __restrict__ Hout,
                                                     const int* __restrict__ mask,
                                                     int applyMask)
{
    int b = blockIdx.x;
    int j = threadIdx.x;                 // 256 threads = one output each
    __shared__ float4 hs4[HGH/4];
    ((float*)hs4)[j] = 0.0f;
    __syncthreads();
    for (int t = 0; t < SS; t++) {
        float acc = XW[(size_t)(b*SS + t) * HGH + j];
        #pragma unroll 8
        for (int k4 = 0; k4 < HGH/4; k4++) {
            float4 w = Wp[(k4 << 8) + j];   // coalesced across warp
            float4 h = hs4[k4];             // broadcast
            acc = fmaf(w.x, h.x, acc);
            acc = fmaf(w.y, h.y, acc);
            acc = fmaf(w.z, h.z, acc);
            acc = fmaf(w.w, h.w, acc);
        }
        float hn = tanhf(acc);
        __syncthreads();
        ((float*)hs4)[j] = hn;
        __syncthreads();
        float o = hn;
        if (applyMask) {
            float mf = (t == 0) ? 1.0f : (float)mask[b*SS0 + (t - 1)];
            o *= mf;
        }
        Hout[(size_t)(b*SS + t) * HGH + j] = o;
    }
}

// ---------------- generic tiled GEMM (BM=BN=64, BK=16, 256 thr, 4x4/thr) ----------------
// C[n][j] = epi( sum_k A[n][k]*B[k][j] (+ optional A2@B2) , ... )
// EPI: 0 = +b1+b2 ; 1 = elu(+b1) ; 2 = tanh(+ pv[n]*wv[j] + b1 + b2) ; 3 = tanh(+b1+b2)

__device__ __forceinline__ void gemm_tile_loop(const float* __restrict__ A,
                                               const float* __restrict__ B,
                                               int K, int J, int n0, int j0, int tid,
                                               float acc[4][4],
                                               float (*As)[64], float (*Bs)[64])
{
    int tx = tid & 15, ty = tid >> 4;
    for (int k0 = 0; k0 < K; k0 += 16) {
        __syncthreads();
        // A tile: 64 rows x 16 k, transposed into As[k][row]
        {
            int row = tid >> 2;
            int kb  = (tid & 3) << 2;
            float4 av = *(const float4*)&A[(size_t)(n0 + row) * K + k0 + kb];
            As[kb + 0][row] = av.x;
            As[kb + 1][row] = av.y;
            As[kb + 2][row] = av.z;
            As[kb + 3][row] = av.w;
        }
        // B tile: 16 k x 64 j
        {
            int row = tid >> 4;
            int cb  = (tid & 15) << 2;
            *(float4*)&Bs[row][cb] = *(const float4*)&B[(size_t)(k0 + row) * J + j0 + cb];
        }
        __syncthreads();
        #pragma unroll
        for (int kk = 0; kk < 16; kk++) {
            float4 a = *(const float4*)&As[kk][ty << 2];
            float4 b = *(const float4*)&Bs[kk][tx << 2];
            acc[0][0] = fmaf(a.x, b.x, acc[0][0]);
            acc[0][1] = fmaf(a.x, b.y, acc[0][1]);
            acc[0][2] = fmaf(a.x, b.z, acc[0][2]);
            acc[0][3] = fmaf(a.x, b.w, acc[0][3]);
            acc[1][0] = fmaf(a.y, b.x, acc[1][0]);
            acc[1][1] = fmaf(a.y, b.y, acc[1][1]);
            acc[1][2] = fmaf(a.y, b.z, acc[1][2]);
            acc[1][3] = fmaf(a.y, b.w, acc[1][3]);
            acc[2][0] = fmaf(a.z, b.x, acc[2][0]);
            acc[2][1] = fmaf(a.z, b.y, acc[2][1]);
            acc[2][2] = fmaf(a.z, b.z, acc[2][2]);
            acc[2][3] = fmaf(a.z, b.w, acc[2][3]);
            acc[3][0] = fmaf(a.w, b.x, acc[3][0]);
            acc[3][1] = fmaf(a.w, b.y, acc[3][1]);
            acc[3][2] = fmaf(a.w, b.z, acc[3][2]);
            acc[3][3] = fmaf(a.w, b.w, acc[3][3]);
        }
    }
}

template<int EPI>
__global__ void __launch_bounds__(256) gemm_kernel(const float* __restrict__ A,
                                                   const float* __restrict__ B,
                                                   const float* __restrict__ A2,
                                                   const float* __restrict__ B2,
                                                   const float* __restrict__ b1,
                                                   const float* __restrict__ b2,
                                                   const float* __restrict__ pv,
                                                   const float* __restrict__ wv,
                                                   float* __restrict__ C,
                                                   int K, int K2, int J)
{
    __shared__ float As[16][64];
    __shared__ float Bs[16][64];
    int tid = threadIdx.x;
    int n0 = blockIdx.x * 64;
    int j0 = blockIdx.y * 64;
    float acc[4][4] = {};
    gemm_tile_loop(A, B, K, J, n0, j0, tid, acc, As, Bs);
    if (A2) gemm_tile_loop(A2, B2, K2, J, n0, j0, tid, acc, As, Bs);

    int tx = tid & 15, ty = tid >> 4;
    int j_base = j0 + (tx << 2);
    #pragma unroll
    for (int i = 0; i < 4; i++) {
        int n = n0 + (ty << 2) + i;
        float r[4];
        #pragma unroll
        for (int l = 0; l < 4; l++) {
            int j = j_base + l;
            float x = acc[i][l];
            if (EPI == 0) {
                x += b1[j] + b2[j];
            } else if (EPI == 1) {
                x += b1[j];
                x = (x > 0.0f) ? x : expm1f(x);
            } else if (EPI == 2) {
                x += pv[n] * wv[j] + b1[j] + b2[j];
                x = tanhf(x);
            } else {
                x += b1[j] + b2[j];
                x = tanhf(x);
            }
            r[l] = x;
        }
        *(float4*)&C[(size_t)n * J + j_base] = make_float4(r[0], r[1], r[2], r[3]);
    }
}

// ---------------- classifier: p[n] = sigmoid(dot(cls_W, h1[n]) + cls_b) ----------------
__global__ void cls_kernel(const float* __restrict__ h1,
                           const float* __restrict__ clsW,
                           const float* __restrict__ clsb,
                           float* __restrict__ pout,
                           float* __restrict__ probs_row)
{
    int gtid = blockIdx.x * blockDim.x + threadIdx.x;
    int n    = gtid >> 5;
    int lane = threadIdx.x & 31;
    if (n >= NN) return;
    const float* row = h1 + (size_t)n * HEH;
    float s = 0.0f;
    #pragma unroll
    for (int j = lane; j < HEH; j += 32) s = fmaf(row[j], clsW[j], s);
    #pragma unroll
    for (int o = 16; o; o >>= 1) s += __shfl_xor_sync(0xFFFFFFFFu, s, o);
    if (lane == 0) {
        float p = 1.0f / (1.0f + expf(-(s + clsb[0])));
        pout[n] = p;
        probs_row[n] = p;
    }
}

// ---------------- arc_logits assembly ----------------
// arc[b, j, i] = (j >= max(0,i-M) && j < i) ? probs[j - max(0,i-M)][b*S + i] : 0
__global__ void arc_kernel(const float* __restrict__ probs, float* __restrict__ arc)
{
    int j = blockIdx.x;
    int b = blockIdx.y;
    int i = threadIdx.x;
    int start = (i - MM > 0) ? (i - MM) : 0;
    float v = 0.0f;
    if (j >= start && j < i) {
        int midx = j - start;   // in [0, M)
        v = probs[(size_t)midx * NN + b * SS + i];
    }
    arc[(size_t)(b * SS + j) * SS + i] = v;
}

// ---------------- host orchestration ----------------
extern "C" void kernel_launch(void* const* d_in, const int* in_sizes, int n_in,
                              void* d_out, int out_size)
{
    const float* input   = (const float*)d_in[0];
    const float* sentinel= (const float*)d_in[1];
    const float* g_Wih0  = (const float*)d_in[2];
    const float* g_Whh0  = (const float*)d_in[3];
    const float* g_bih0  = (const float*)d_in[4];
    const float* g_bhh0  = (const float*)d_in[5];
    const float* g_Wih1  = (const float*)d_in[6];
    const float* g_Whh1  = (const float*)d_in[7];
    const float* g_bih1  = (const float*)d_in[8];
    const float* g_bhh1  = (const float*)d_in[9];
    const float* e_Wih0  = (const float*)d_in[10];
    const float* e_Whh0  = (const float*)d_in[11];
    const float* e_bih0  = (const float*)d_in[12];
    const float* e_bhh0  = (const float*)d_in[13];
    const float* e_Wih1  = (const float*)d_in[14];
    const float* e_Whh1  = (const float*)d_in[15];
    const float* e_bih1  = (const float*)d_in[16];
    const float* e_bhh1  = (const float*)d_in[17];
    const float* cls_W   = (const float*)d_in[18];
    const float* cls_b   = (const float*)d_in[19];
    const float* head_W  = (const float*)d_in[20];
    const float* head_b  = (const float*)d_in[21];
    const float* dep_W   = (const float*)d_in[22];
    const float* dep_b   = (const float*)d_in[23];
    const int*   mask    = (const int*)  d_in[24];
    (void)d_in; (void)in_sizes; (void)n_in;

    float* out = (float*)d_out;
    float* out_head = out;                       // B*S*T
    float* out_dep  = out + (size_t)NN * TT;     // B*S*T
    float* out_arc  = out + (size_t)2 * NN * TT; // B*S*S
    (void)out_size;

    float *pX, *pXW, *pH0, *pGS, *ph0a, *ph0b, *ph1a, *ph1b, *pzero, *ppa, *ppb, *pones, *pprobs;
    float *pWTih0g, *pWTih1g, *pWThh0e, *pWTih1e, *pWThh1e, *pWThead, *pWTdep;
    float4 *pWp0, *pWp1;
    cudaGetSymbolAddress((void**)&pX, d_X);
    cudaGetSymbolAddress((void**)&pXW, d_XW);
    cudaGetSymbolAddress((void**)&pH0, d_H0);
    cudaGetSymbolAddress((void**)&pGS, d_GS);
    cudaGetSymbolAddress((void**)&ph0a, d_h0a);
    cudaGetSymbolAddress((void**)&ph0b, d_h0b);
    cudaGetSymbolAddress((void**)&ph1a, d_h1a);
    cudaGetSymbolAddress((void**)&ph1b, d_h1b);
    cudaGetSymbolAddress((void**)&pzero, d_zero);
    cudaGetSymbolAddress((void**)&ppa, d_pa);
    cudaGetSymbolAddress((void**)&ppb, d_pb);
    cudaGetSymbolAddress((void**)&pones, d_ones);
    cudaGetSymbolAddress((void**)&pprobs, d_probs);
    cudaGetSymbolAddress((void**)&pWTih0g, d_WT_ih0g);
    cudaGetSymbolAddress((void**)&pWTih1g, d_WT_ih1g);
    cudaGetSymbolAddress((void**)&pWp0, d_Wp0);
    cudaGetSymbolAddress((void**)&pWp1, d_Wp1);
    cudaGetSymbolAddress((void**)&pWThh0e, d_WT_hh0e);
    cudaGetSymbolAddress((void**)&pWTih1e, d_WT_ih1e);
    cudaGetSymbolAddress((void**)&pWThh1e, d_WT_hh1e);
    cudaGetSymbolAddress((void**)&pWThead, d_WT_head);
    cudaGetSymbolAddress((void**)&pWTdep, d_WT_dep);

    // prep
    build_x_kernel<<<(NN*DD/4)/256, 256>>>(input, sentinel, pX);
    init_ones_kernel<<<(NN + 255)/256, 256>>>(pones);
    cudaMemsetAsync(pzero, 0, (size_t)NN * HEH * sizeof(float));

    dim3 tb(32, 8);
    transpose_kernel<<<dim3(DD/32,  HGH/32), tb>>>(g_Wih0, pWTih0g, HGH, DD);
    transpose_kernel<<<dim3(HGH/32, HGH/32), tb>>>(g_Wih1, pWTih1g, HGH, HGH);
    transpose_kernel<<<dim3(HEH/32, HEH/32), tb>>>(e_Whh0, pWThh0e, HEH, HEH);
    transpose_kernel<<<dim3(HEH/32, HEH/32), tb>>>(e_Wih1, pWTih1e, HEH, HEH);
    transpose_kernel<<<dim3(HEH/32, HEH/32), tb>>>(e_Whh1, pWThh1e, HEH, HEH);
    transpose_kernel<<<dim3(HGH/32, TT/32),  tb>>>(head_W, pWThead, TT, HGH);
    transpose_kernel<<<dim3(HGH/32, TT/32),  tb>>>(dep_W,  pWTdep,  TT, HGH);
    pack_whh_kernel<<<64, 256>>>(g_Whh0, pWp0);
    pack_whh_kernel<<<64, 256>>>(g_Whh1, pWp1);

    // g-RNN layer 0: XW0 = X @ Wih0^T + bih0 + bhh0 ; scan -> H0
    gemm_kernel<0><<<dim3(NN/64, HGH/64), 256>>>(pX, pWTih0g, nullptr, nullptr,
        g_bih0, g_bhh0, nullptr, nullptr, pXW, DD, 0, HGH);
    scan_g_kernel<<<BB, 256>>>(pXW, pWp0, pH0, nullptr, 0);

    // layer 1: XW1 = H0 @ Wih1^T + biases ; scan (with mask on output) -> GS
    gemm_kernel<0><<<dim3(NN/64, HGH/64), 256>>>(pH0, pWTih1g, nullptr, nullptr,
        g_bih1, g_bhh1, nullptr, nullptr, pXW, HGH, 0, HGH);
    scan_g_kernel<<<BB, 256>>>(pXW, pWp1, pGS, mask, 1);

    // tags: elu(GS @ W^T + b) straight into output
    gemm_kernel<1><<<dim3(NN/64, TT/64), 256>>>(pGS, pWThead, nullptr, nullptr,
        head_b, nullptr, nullptr, nullptr, out_head, HGH, 0, TT);
    gemm_kernel<1><<<dim3(NN/64, TT/64), 256>>>(pGS, pWTdep, nullptr, nullptr,
        dep_b, nullptr, nullptr, nullptr, out_dep, HGH, 0, TT);

    // edge scan: M=32 steps
    float* h0buf[2] = {ph0a, ph0b};
    float* h1buf[2] = {ph1a, ph1b};
    float* pbuf[2]  = {ppa, ppb};
    for (int m = 0; m < MM; m++) {
        const float* h0s = (m == 0) ? pGS   : h0buf[(m - 1) & 1];
        const float* h1s = (m == 0) ? pzero : h1buf[(m - 1) & 1];
        const float* ps  = (m == 0) ? pones : pbuf[(m - 1) & 1];
        float* h0d = h0buf[m & 1];
        float* h1d = h1buf[m & 1];
        float* pd  = pbuf[m & 1];

        // h0 = tanh(p*w0 + c0 + h0 @ Whh0^T)
        gemm_kernel<2><<<dim3(NN/64, HEH/64), 256>>>(h0s, pWThh0e, nullptr, nullptr,
            e_bih0, e_bhh0, ps, e_Wih0, h0d, HEH, 0, HEH);
        // h1 = tanh(h0_new @ Wih1^T + c1 + h1 @ Whh1^T)
        gemm_kernel<3><<<dim3(NN/64, HEH/64), 256>>>(h0d, pWTih1e, h1s, pWThh1e,
            e_bih1, e_bhh1, nullptr, nullptr, h1d, HEH, HEH, HEH);
        // p = sigmoid(h1_new . cls_W + cls_b); probs[m] = p
        cls_kernel<<<(NN*32)/256, 256>>>(h1d, cls_W, cls_b, pd, pprobs + (size_t)m * NN);
    }

    // arc_logits
    arc_kernel<<<dim3(SS, BB), SS>>>(pprobs, out_arc);
}

// round 3
// speedup vs baseline: 1.4407x; 1.4407x over previous
#include <cuda_runtime.h>
#include <math.h>
#include <stdint.h>

// Problem constants
#define BB   16
#define SS   512
#define SS0  511
#define DD   512
#define HGH  256
#define HEH  256
#define TT   128
#define MM   32
#define NN   (BB*SS)   // 8192

#define ROWS_PER_CTA 64
#define HST 260      // h-state smem row stride (conflict-free for A frags)
#define BST 264      // B tile smem row stride (conflict-free for B frags)

// ---------------- device scratch ----------------
__device__ float  d_X   [NN*DD];
__device__ float  d_XW  [NN*HGH];
__device__ float  d_H0  [NN*HGH];
__device__ float  d_GS  [NN*HGH];
__device__ float  d_probs[MM*NN];

__device__ float  d_WT_ih0g[DD*HGH];
__device__ float  d_WT_ih1g[HGH*HGH];
__device__ float4 d_Wp0[(HGH/4)*HGH];
__device__ float4 d_Wp1[(HGH/4)*HGH];
__device__ float  d_WT_hh0e[HEH*HEH];  // tf32-rounded, K-major
__device__ float  d_WT_ih1e[HEH*HEH];  // tf32-rounded
__device__ float  d_WT_hh1e[HEH*HEH];  // tf32-rounded
__device__ float  d_WT_head[HGH*TT];
__device__ float  d_WT_dep [HGH*TT];

// ---------------- helpers ----------------
__device__ __forceinline__ uint32_t f2tf32(float x) {
    uint32_t r;
    asm("cvt.rna.tf32.f32 %0, %1;" : "=r"(r) : "f"(x));
    return r;
}

__device__ __forceinline__ void mma_tf32(float& c0, float& c1, float& c2, float& c3,
                                         uint32_t a0, uint32_t a1, uint32_t a2, uint32_t a3,
                                         uint32_t b0, uint32_t b1) {
    asm volatile("mma.sync.aligned.m16n8k8.row.col.f32.tf32.tf32.f32 "
        "{%0,%1,%2,%3}, {%4,%5,%6,%7}, {%8,%9}, {%0,%1,%2,%3};"
        : "+f"(c0), "+f"(c1), "+f"(c2), "+f"(c3)
        : "r"(a0), "r"(a1), "r"(a2), "r"(a3), "r"(b0), "r"(b1));
}

// ---------------- prep kernels ----------------
__global__ void build_x_kernel(const float* __restrict__ input,
                               const float* __restrict__ sent,
                               float* __restrict__ X)
{
    int idx = blockIdx.x * blockDim.x + threadIdx.x;
    int n  = idx >> 7;
    int k4 = idx & 127;
    int b = n >> 9, s = n & 511;
    float4 v;
    if (s == 0) v = ((const float4*)sent)[k4];
    else        v = ((const float4*)input)[(size_t)((b*SS0 + s - 1) << 7) + k4];
    ((float4*)X)[idx] = v;
}

// transpose in (R x C) -> out (C x R); TF32 flag rounds values to tf32
__global__ void transpose_kernel(const float* __restrict__ in, float* __restrict__ out,
                                 int R, int C, int tf32)
{
    __shared__ float tile[32][33];
    int c0 = blockIdx.x * 32, r0 = blockIdx.y * 32;
    int x = threadIdx.x, y = threadIdx.y;
    #pragma unroll
    for (int dy = 0; dy < 32; dy += 8) {
        int r = r0 + y + dy, c = c0 + x;
        if (r < R && c < C) tile[y + dy][x] = in[(size_t)r * C + c];
    }
    __syncthreads();
    #pragma unroll
    for (int dy = 0; dy < 32; dy += 8) {
        int r = r0 + x, c = c0 + y + dy;
        if (r < R && c < C) {
            float v = tile[x][y + dy];
            if (tf32) v = __uint_as_float(f2tf32(v));
            out[(size_t)c * R + r] = v;
        }
    }
}

__global__ void pack_whh_kernel(const float* __restrict__ W, float4* __restrict__ Wp)
{
    int idx = blockIdx.x * blockDim.x + threadIdx.x;
    int k4 = idx >> 8, j = idx & 255;
    const float* src = W + (size_t)j * HGH + (k4 << 2);
    Wp[idx] = make_float4(src[0], src[1], src[2], src[3]);
}

// ---------------- g-RNN recurrence: one CTA per batch element ----------------
__global__ void __launch_bounds__(256) scan_g_kernel(const float* __restrict__ XW,
                                                     const float4* __restrict__ Wp,
                                                     float* __restrict__ Hout,
                                                     const int* __restrict__ mask,
                                                     int applyMask)
{
    int b = blockIdx.x;
    int j = threadIdx.x;
    __shared__ float4 hs4[HGH/4];
    ((float*)hs4)[j] = 0.0f;
    __syncthreads();
    for (int t = 0; t < SS; t++) {
        float acc = XW[(size_t)(b*SS + t) * HGH + j];
        #pragma unroll 8
        for (int k4 = 0; k4 < HGH/4; k4++) {
            float4 w = Wp[(k4 << 8) + j];
            float4 h = hs4[k4];
            acc = fmaf(w.x, h.x, acc);
            acc = fmaf(w.y, h.y, acc);
            acc = fmaf(w.z, h.z, acc);
            acc = fmaf(w.w, h.w, acc);
        }
        float hn = tanhf(acc);
        __syncthreads();
        ((float*)hs4)[j] = hn;
        __syncthreads();
        float o = hn;
        if (applyMask) {
            float mf = (t == 0) ? 1.0f : (float)mask[b*SS0 + (t - 1)];
            o *= mf;
        }
        Hout[(size_t)(b*SS + t) * HGH + j] = o;
    }
}

// ---------------- generic tiled SIMT GEMM (input proj + tags) ----------------
__device__ __forceinline__ void gemm_tile_loop(const float* __restrict__ A,
                                               const float* __restrict__ B,
                                               int K, int J, int n0, int j0, int tid,
                                               float acc[4][4],
                                               float (*As)[64], float (*Bs)[64])
{
    int tx = tid & 15, ty = tid >> 4;
    for (int k0 = 0; k0 < K; k0 += 16) {
        __syncthreads();
        {
            int row = tid >> 2;
            int kb  = (tid & 3) << 2;
            float4 av = *(const float4*)&A[(size_t)(n0 + row) * K + k0 + kb];
            As[kb + 0][row] = av.x;
            As[kb + 1][row] = av.y;
            As[kb + 2][row] = av.z;
            As[kb + 3][row] = av.w;
        }
        {
            int row = tid >> 4;
            int cb  = (tid & 15) << 2;
            *(float4*)&Bs[row][cb] = *(const float4*)&B[(size_t)(k0 + row) * J + j0 + cb];
        }
        __syncthreads();
        #pragma unroll
        for (int kk = 0; kk < 16; kk++) {
            float4 a = *(const float4*)&As[kk][ty << 2];
            float4 b = *(const float4*)&Bs[kk][tx << 2];
            acc[0][0] = fmaf(a.x, b.x, acc[0][0]);
            acc[0][1] = fmaf(a.x, b.y, acc[0][1]);
            acc[0][2] = fmaf(a.x, b.z, acc[0][2]);
            acc[0][3] = fmaf(a.x, b.w, acc[0][3]);
            acc[1][0] = fmaf(a.y, b.x, acc[1][0]);
            acc[1][1] = fmaf(a.y, b.y, acc[1][1]);
            acc[1][2] = fmaf(a.y, b.z, acc[1][2]);
            acc[1][3] = fmaf(a.y, b.w, acc[1][3]);
            acc[2][0] = fmaf(a.z, b.x, acc[2][0]);
            acc[2][1] = fmaf(a.z, b.y, acc[2][1]);
            acc[2][2] = fmaf(a.z, b.z, acc[2][2]);
            acc[2][3] = fmaf(a.z, b.w, acc[2][3]);
            acc[3][0] = fmaf(a.w, b.x, acc[3][0]);
            acc[3][1] = fmaf(a.w, b.y, acc[3][1]);
            acc[3][2] = fmaf(a.w, b.z, acc[3][2]);
            acc[3][3] = fmaf(a.w, b.w, acc[3][3]);
        }
    }
}

// EPI: 0 = +b1+b2 ; 1 = elu(+b1)
template<int EPI>
__global__ void __launch_bounds__(256) gemm_kernel(const float* __restrict__ A,
                                                   const float* __restrict__ B,
                                                   const float* __restrict__ b1,
                                                   const float* __restrict__ b2,
                                                   float* __restrict__ C,
                                                   int K, int J)
{
    __shared__ float As[16][64];
    __shared__ float Bs[16][64];
    int tid = threadIdx.x;
    int n0 = blockIdx.x * 64;
    int j0 = blockIdx.y * 64;
    float acc[4][4] = {};
    gemm_tile_loop(A, B, K, J, n0, j0, tid, acc, As, Bs);

    int tx = tid & 15, ty = tid >> 4;
    int j_base = j0 + (tx << 2);
    #pragma unroll
    for (int i = 0; i < 4; i++) {
        int n = n0 + (ty << 2) + i;
        float r[4];
        #pragma unroll
        for (int l = 0; l < 4; l++) {
            int j = j_base + l;
            float x = acc[i][l];
            if (EPI == 0) {
                x += b1[j] + b2[j];
            } else {
                x += b1[j];
                x = (x > 0.0f) ? x : expm1f(x);
            }
            r[l] = x;
        }
        *(float4*)&C[(size_t)n * J + j_base] = make_float4(r[0], r[1], r[2], r[3]);
    }
}

// ---------------- fused edge scan (tf32 tensor cores, state resident in smem) ----
// Each CTA: 64 rows. 8 warps; warp tile 32x64 (2 m-tiles x 8 n-tiles of m16n8k8).
// smem layout (floats): h0s[64*HST], h1s[64*HST], ps[64], w0s[256], bc0[256],
//                       bc1[256], clw[256], Bs[32*BST]

__device__ __forceinline__ void edge_gemm_accum(const float* __restrict__ As,  // smem state
                                                const float* __restrict__ Bg,  // global tf32 KxN
                                                float* __restrict__ Bs,
                                                float acc[2][8][4],
                                                int rg, int cg, int gid, int tig, int tid)
{
    #pragma unroll 1
    for (int k0 = 0; k0 < 256; k0 += 32) {
        __syncthreads();
        // stage B chunk (32 x 256) into smem, coalesced float4
        #pragma unroll
        for (int i = 0; i < 8; i++) {
            int f = tid + i*256;
            int r = f >> 6, c4 = f & 63;
            float4 v = *(const float4*)&Bg[(size_t)(k0 + r)*256 + (c4<<2)];
            *(float4*)&Bs[r*BST + (c4<<2)] = v;
        }
        __syncthreads();
        #pragma unroll
        for (int ks = 0; ks < 4; ks++) {
            int kk = ks*8;
            uint32_t a[2][4];
            #pragma unroll
            for (int mt = 0; mt < 2; mt++) {
                int row0 = rg*32 + mt*16 + gid;
                int kc = k0 + kk + tig;
                a[mt][0] = f2tf32(As[(size_t) row0   *HST + kc]);
                a[mt][1] = f2tf32(As[(size_t)(row0+8)*HST + kc]);
                a[mt][2] = f2tf32(As[(size_t) row0   *HST + kc+4]);
                a[mt][3] = f2tf32(As[(size_t)(row0+8)*HST + kc+4]);
            }
            #pragma unroll
            for (int nt = 0; nt < 8; nt++) {
                int col = cg*64 + nt*8 + gid;
                uint32_t b0 = __float_as_uint(Bs[(kk+tig)  *BST + col]);
                uint32_t b1 = __float_as_uint(Bs[(kk+tig+4)*BST + col]);
                #pragma unroll
                for (int mt = 0; mt < 2; mt++) {
                    mma_tf32(acc[mt][nt][0], acc[mt][nt][1], acc[mt][nt][2], acc[mt][nt][3],
                             a[mt][0], a[mt][1], a[mt][2], a[mt][3], b0, b1);
                }
            }
        }
    }
}

__global__ void __launch_bounds__(256, 1) edge_fused_kernel(
    const float* __restrict__ gs,
    const float* __restrict__ Whh0T,
    const float* __restrict__ Wih1T,
    const float* __restrict__ Whh1T,
    const float* __restrict__ w0,
    const float* __restrict__ bih0, const float* __restrict__ bhh0,
    const float* __restrict__ bih1, const float* __restrict__ bhh1,
    const float* __restrict__ clsW, const float* __restrict__ clsb,
    float* __restrict__ probs)
{
    extern __shared__ float sm[];
    float* h0s = sm;
    float* h1s = h0s + ROWS_PER_CTA*HST;
    float* ps  = h1s + ROWS_PER_CTA*HST;
    float* w0s = ps + ROWS_PER_CTA;
    float* bc0 = w0s + 256;
    float* bc1 = bc0 + 256;
    float* clw = bc1 + 256;
    float* Bs  = clw + 256;
    __shared__ float s_clsb;

    int tid = threadIdx.x;
    int lane = tid & 31, warp = tid >> 5;
    int gid = lane >> 2, tig = lane & 3;
    int rg = warp >> 2, cg = warp & 3;
    int n0 = blockIdx.x * ROWS_PER_CTA;

    // consts
    w0s[tid] = w0[tid];
    bc0[tid] = bih0[tid] + bhh0[tid];
    bc1[tid] = bih1[tid] + bhh1[tid];
    clw[tid] = clsW[tid];
    if (tid == 0) s_clsb = clsb[0];

    // init state: h0 = gs rows, h1 = 0, p = 1
    #pragma unroll
    for (int i = tid; i < ROWS_PER_CTA*256; i += 256) {
        int r = i >> 8, c = i & 255;
        h0s[r*HST + c] = gs[(size_t)(n0 + r)*256 + c];
        h1s[r*HST + c] = 0.0f;
    }
    if (tid < ROWS_PER_CTA) ps[tid] = 1.0f;
    __syncthreads();

    float acc[2][8][4];

    for (int m = 0; m < MM; m++) {
        // ---- h0_new = tanh(h0 @ Whh0^T + p*w0 + bc0) ----
        #pragma unroll
        for (int mt=0;mt<2;mt++)
            #pragma unroll
            for (int nt=0;nt<8;nt++)
                #pragma unroll
                for (int q=0;q<4;q++) acc[mt][nt][q] = 0.0f;

        edge_gemm_accum(h0s, Whh0T, Bs, acc, rg, cg, gid, tig, tid);

        __syncthreads();
        #pragma unroll
        for (int mt=0;mt<2;mt++) {
            #pragma unroll
            for (int nt=0;nt<8;nt++) {
                #pragma unroll
                for (int q=0;q<4;q++) {
                    int row = rg*32 + mt*16 + gid + ((q>>1)<<3);
                    int col = cg*64 + nt*8 + tig*2 + (q&1);
                    float x = acc[mt][nt][q] + ps[row]*w0s[col] + bc0[col];
                    h0s[row*HST + col] = tanhf(x);
                }
            }
        }
        __syncthreads();

        // ---- h1_new = tanh(h0_new @ Wih1^T + h1 @ Whh1^T + bc1) ----
        #pragma unroll
        for (int mt=0;mt<2;mt++)
            #pragma unroll
            for (int nt=0;nt<8;nt++)
                #pragma unroll
                for (int q=0;q<4;q++) acc[mt][nt][q] = 0.0f;

        edge_gemm_accum(h0s, Wih1T, Bs, acc, rg, cg, gid, tig, tid);
        edge_gemm_accum(h1s, Whh1T, Bs, acc, rg, cg, gid, tig, tid);

        __syncthreads();
        #pragma unroll
        for (int mt=0;mt<2;mt++) {
            #pragma unroll
            for (int nt=0;nt<8;nt++) {
                #pragma unroll
                for (int q=0;q<4;q++) {
                    int row = rg*32 + mt*16 + gid + ((q>>1)<<3);
                    int col = cg*64 + nt*8 + tig*2 + (q&1);
                    float x = acc[mt][nt][q] + bc1[col];
                    h1s[row*HST + col] = tanhf(x);
                }
            }
        }
        __syncthreads();

        // ---- p = sigmoid(h1 . clsW + clsb) ----
        #pragma unroll
        for (int i = 0; i < 8; i++) {
            int r = warp*8 + i;
            float s = 0.0f;
            #pragma unroll
            for (int c = lane; c < 256; c += 32)
                s = fmaf(h1s[r*HST + c], clw[c], s);
            #pragma unroll
            for (int o = 16; o; o >>= 1) s += __shfl_xor_sync(0xFFFFFFFFu, s, o);
            if (lane == 0) {
                float p = 1.0f / (1.0f + expf(-(s + s_clsb)));
                ps[r] = p;
                probs[(size_t)m*NN + n0 + r] = p;
            }
        }
        __syncthreads();
    }
}

// ---------------- arc_logits assembly ----------------
__global__ void arc_kernel(const float* __restrict__ probs, float* __restrict__ arc)
{
    int j = blockIdx.x;
    int b = blockIdx.y;
    int i = threadIdx.x;
    int start = (i - MM > 0) ? (i - MM) : 0;
    float v = 0.0f;
    if (j >= start && j < i) {
        int midx = j - start;
        v = probs[(size_t)midx * NN + b * SS + i];
    }
    arc[(size_t)(b * SS + j) * SS + i] = v;
}

// ---------------- host orchestration ----------------
static const int EDGE_SMEM_BYTES =
    (2*ROWS_PER_CTA*HST + ROWS_PER_CTA + 4*256 + 32*BST) * (int)sizeof(float);

extern "C" void kernel_launch(void* const* d_in, const int* in_sizes, int n_in,
                              void* d_out, int out_size)
{
    const float* input   = (const float*)d_in[0];
    const float* sentinel= (const float*)d_in[1];
    const float* g_Wih0  = (const float*)d_in[2];
    const float* g_Whh0  = (const float*)d_in[3];
    const float* g_bih0  = (const float*)d_in[4];
    const float* g_bhh0  = (const float*)d_in[5];
    const float* g_Wih1  = (const float*)d_in[6];
    const float* g_Whh1  = (const float*)d_in[7];
    const float* g_bih1  = (const float*)d_in[8];
    const float* g_bhh1  = (const float*)d_in[9];
    const float* e_Wih0  = (const float*)d_in[10];
    const float* e_Whh0  = (const float*)d_in[11];
    const float* e_bih0  = (const float*)d_in[12];
    const float* e_bhh0  = (const float*)d_in[13];
    const float* e_Wih1  = (const float*)d_in[14];
    const float* e_Whh1  = (const float*)d_in[15];
    const float* e_bih1  = (const float*)d_in[16];
    const float* e_bhh1  = (const float*)d_in[17];
    const float* cls_W   = (const float*)d_in[18];
    const float* cls_b   = (const float*)d_in[19];
    const float* head_W  = (const float*)d_in[20];
    const float* head_b  = (const float*)d_in[21];
    const float* dep_W   = (const float*)d_in[22];
    const float* dep_b   = (const float*)d_in[23];
    const int*   mask    = (const int*)  d_in[24];
    (void)in_sizes; (void)n_in; (void)out_size;

    float* out = (float*)d_out;
    float* out_head = out;
    float* out_dep  = out + (size_t)NN * TT;
    float* out_arc  = out + (size_t)2 * NN * TT;

    float *pX, *pXW, *pH0, *pGS, *pprobs;
    float *pWTih0g, *pWTih1g, *pWThh0e, *pWTih1e, *pWThh1e, *pWThead, *pWTdep;
    float4 *pWp0, *pWp1;
    cudaGetSymbolAddress((void**)&pX, d_X);
    cudaGetSymbolAddress((void**)&pXW, d_XW);
    cudaGetSymbolAddress((void**)&pH0, d_H0);
    cudaGetSymbolAddress((void**)&pGS, d_GS);
    cudaGetSymbolAddress((void**)&pprobs, d_probs);
    cudaGetSymbolAddress((void**)&pWTih0g, d_WT_ih0g);
    cudaGetSymbolAddress((void**)&pWTih1g, d_WT_ih1g);
    cudaGetSymbolAddress((void**)&pWp0, d_Wp0);
    cudaGetSymbolAddress((void**)&pWp1, d_Wp1);
    cudaGetSymbolAddress((void**)&pWThh0e, d_WT_hh0e);
    cudaGetSymbolAddress((void**)&pWTih1e, d_WT_ih1e);
    cudaGetSymbolAddress((void**)&pWThh1e, d_WT_hh1e);
    cudaGetSymbolAddress((void**)&pWThead, d_WT_head);
    cudaGetSymbolAddress((void**)&pWTdep, d_WT_dep);

    cudaFuncSetAttribute(edge_fused_kernel,
                         cudaFuncAttributeMaxDynamicSharedMemorySize, EDGE_SMEM_BYTES);

    // prep
    build_x_kernel<<<(NN*DD/4)/256, 256>>>(input, sentinel, pX);

    dim3 tb(32, 8);
    transpose_kernel<<<dim3(DD/32,  HGH/32), tb>>>(g_Wih0, pWTih0g, HGH, DD, 0);
    transpose_kernel<<<dim3(HGH/32, HGH/32), tb>>>(g_Wih1, pWTih1g, HGH, HGH, 0);
    transpose_kernel<<<dim3(HEH/32, HEH/32), tb>>>(e_Whh0, pWThh0e, HEH, HEH, 1);
    transpose_kernel<<<dim3(HEH/32, HEH/32), tb>>>(e_Wih1, pWTih1e, HEH, HEH, 1);
    transpose_kernel<<<dim3(HEH/32, HEH/32), tb>>>(e_Whh1, pWThh1e, HEH, HEH, 1);
    transpose_kernel<<<dim3(HGH/32, TT/32),  tb>>>(head_W, pWThead, TT, HGH, 0);
    transpose_kernel<<<dim3(HGH/32, TT/32),  tb>>>(dep_W,  pWTdep,  TT, HGH, 0);
    pack_whh_kernel<<<64, 256>>>(g_Whh0, pWp0);
    pack_whh_kernel<<<64, 256>>>(g_Whh1, pWp1);

    // g-RNN layer 0
    gemm_kernel<0><<<dim3(NN/64, HGH/64), 256>>>(pX, pWTih0g, g_bih0, g_bhh0, pXW, DD, HGH);
    scan_g_kernel<<<BB, 256>>>(pXW, pWp0, pH0, nullptr, 0);

    // g-RNN layer 1 (mask applied on output)
    gemm_kernel<0><<<dim3(NN/64, HGH/64), 256>>>(pH0, pWTih1g, g_bih1, g_bhh1, pXW, HGH, HGH);
    scan_g_kernel<<<BB, 256>>>(pXW, pWp1, pGS, mask, 1);

    // tags
    gemm_kernel<1><<<dim3(NN/64, TT/64), 256>>>(pGS, pWThead, head_b, nullptr, out_head, HGH, TT);
    gemm_kernel<1><<<dim3(NN/64, TT/64), 256>>>(pGS, pWTdep,  dep_b,  nullptr, out_dep,  HGH, TT);

    // fused edge scan (all 32 steps, state resident)
    edge_fused_kernel<<<NN/ROWS_PER_CTA, 256, EDGE_SMEM_BYTES>>>(
        pGS, pWThh0e, pWTih1e, pWThh1e,
        e_Wih0, e_bih0, e_bhh0, e_bih1, e_bhh1,
        cls_W, cls_b, pprobs);

    // arc_logits
    arc_kernel<<<dim3(SS, BB), SS>>>(pprobs, out_arc);
}

// round 4
// speedup vs baseline: 2.8084x; 1.9493x over previous
#include <cuda_runtime.h>
#include <math.h>
#include <stdint.h>

// Problem constants
#define BB   16
#define SS   512
#define SS0  511
#define DD   512
#define HGH  256
#define HEH  256
#define TT   128
#define MM   32
#define NN   (BB*SS)   // 8192

#define ROWS_PER_CTA 64
#define HST 260      // h-state smem row stride (conflict-free for A frags)
#define BST 264      // B tile smem row stride (conflict-free for B frags)

// ---------------- device scratch ----------------
__device__ float  d_X   [NN*DD];
__device__ float  d_XW  [NN*HGH];
__device__ float  d_H0  [NN*HGH];
__device__ float  d_GS  [NN*HGH];
__device__ float  d_probs[MM*NN];

__device__ float  d_WT_ih0g[DD*HGH];
__device__ float  d_WT_ih1g[HGH*HGH];
__device__ float4 d_Wp0[(HGH/4)*HGH];
__device__ float4 d_Wp1[(HGH/4)*HGH];
__device__ float  d_WT_hh0e[HEH*HEH];  // tf32-rounded, K-major
__device__ float  d_WT_ih1e[HEH*HEH];  // tf32-rounded
__device__ float  d_WT_hh1e[HEH*HEH];  // tf32-rounded
__device__ float  d_WT_head[HGH*TT];
__device__ float  d_WT_dep [HGH*TT];

// ---------------- helpers ----------------
__device__ __forceinline__ uint32_t f2tf32(float x) {
    uint32_t r;
    asm("cvt.rna.tf32.f32 %0, %1;" : "=r"(r) : "f"(x));
    return r;
}

__device__ __forceinline__ float fast_tanh(float x) {
    float y;
    asm("tanh.approx.f32 %0, %1;" : "=f"(y) : "f"(x));
    return y;
}

__device__ __forceinline__ void mma_tf32(float& c0, float& c1, float& c2, float& c3,
                                         uint32_t a0, uint32_t a1, uint32_t a2, uint32_t a3,
                                         uint32_t b0, uint32_t b1) {
    asm volatile("mma.sync.aligned.m16n8k8.row.col.f32.tf32.tf32.f32 "
        "{%0,%1,%2,%3}, {%4,%5,%6,%7}, {%8,%9}, {%0,%1,%2,%3};"
        : "+f"(c0), "+f"(c1), "+f"(c2), "+f"(c3)
        : "r"(a0), "r"(a1), "r"(a2), "r"(a3), "r"(b0), "r"(b1));
}

// ---------------- single fused prep kernel (task-switched) ----------------
// task 0: build X       (4096 blocks)
// task 1..7: transposes (<=128 blocks each)
// task 8,9: pack Whh    (64 blocks)
__device__ __forceinline__ void prep_transpose(const float* __restrict__ in,
                                               float* __restrict__ out,
                                               int R, int C, int tf32, int bx, int tid)
{
    int tilesC = C >> 5, tilesR = R >> 5;
    if (bx >= tilesC * tilesR) return;
    int c0 = (bx % tilesC) << 5;
    int r0 = (bx / tilesC) << 5;
    __shared__ float tile[32][33];
    int x = tid & 31, y = tid >> 5;   // 32 x 8
    #pragma unroll
    for (int dy = 0; dy < 32; dy += 8)
        tile[y + dy][x] = in[(size_t)(r0 + y + dy) * C + c0 + x];
    __syncthreads();
    #pragma unroll
    for (int dy = 0; dy < 32; dy += 8) {
        float v = tile[x][y + dy];
        if (tf32) v = __uint_as_float(f2tf32(v));
        out[(size_t)(c0 + y + dy) * R + r0 + x] = v;
    }
}

__global__ void __launch_bounds__(256) prep_kernel(
    const float* __restrict__ input, const float* __restrict__ sent,
    const float* __restrict__ g_Wih0, const float* __restrict__ g_Wih1,
    const float* __restrict__ e_Whh0, const float* __restrict__ e_Wih1,
    const float* __restrict__ e_Whh1,
    const float* __restrict__ head_W, const float* __restrict__ dep_W,
    const float* __restrict__ g_Whh0, const float* __restrict__ g_Whh1,
    float* __restrict__ X,
    float* __restrict__ WTih0g, float* __restrict__ WTih1g,
    float* __restrict__ WThh0e, float* __restrict__ WTih1e, float* __restrict__ WThh1e,
    float* __restrict__ WThead, float* __restrict__ WTdep,
    float4* __restrict__ Wp0, float4* __restrict__ Wp1)
{
    int task = blockIdx.y;
    int bx   = blockIdx.x;
    int tid  = threadIdx.x;
    if (task == 0) {
        int idx = bx * 256 + tid;           // over NN*DD/4 float4s
        int n  = idx >> 7;
        int k4 = idx & 127;
        int b = n >> 9, s = n & 511;
        float4 v;
        if (s == 0) v = ((const float4*)sent)[k4];
        else        v = ((const float4*)input)[(size_t)((b*SS0 + s - 1) << 7) + k4];
        ((float4*)X)[idx] = v;
    } else if (task == 1) {
        prep_transpose(g_Wih0, WTih0g, HGH, DD, 0, bx, tid);
    } else if (task == 2) {
        prep_transpose(g_Wih1, WTih1g, HGH, HGH, 0, bx, tid);
    } else if (task == 3) {
        prep_transpose(e_Whh0, WThh0e, HEH, HEH, 1, bx, tid);
    } else if (task == 4) {
        prep_transpose(e_Wih1, WTih1e, HEH, HEH, 1, bx, tid);
    } else if (task == 5) {
        prep_transpose(e_Whh1, WThh1e, HEH, HEH, 1, bx, tid);
    } else if (task == 6) {
        prep_transpose(head_W, WThead, TT, HGH, 0, bx, tid);
    } else if (task == 7) {
        prep_transpose(dep_W, WTdep, TT, HGH, 0, bx, tid);
    } else if (task == 8 || task == 9) {
        if (bx >= 64) return;
        const float* W = (task == 8) ? g_Whh0 : g_Whh1;
        float4* Wp = (task == 8) ? Wp0 : Wp1;
        int idx = bx * 256 + tid;
        int k4 = idx >> 8, j = idx & 255;
        const float* src = W + (size_t)j * HGH + (k4 << 2);
        Wp[idx] = make_float4(src[0], src[1], src[2], src[3]);
    }
}

// ---------------- g-RNN recurrence: one CTA per batch element ----------------
// 4 accumulators (break FMA chain) + prefetched W groups (8 float4 in flight)
__global__ void __launch_bounds__(256, 1) scan_g_kernel(const float* __restrict__ XW,
                                                        const float4* __restrict__ Wp,
                                                        float* __restrict__ Hout,
                                                        const int* __restrict__ mask,
                                                        int applyMask)
{
    int b = blockIdx.x;
    int j = threadIdx.x;
    __shared__ float4 hs4[2][HGH/4];   // double buffer: write next while others read cur
    ((float*)hs4[0])[j] = 0.0f;
    __syncthreads();
    int cur = 0;
    const float* xwrow = XW + (size_t)b * SS * HGH + j;
    for (int t = 0; t < SS; t++) {
        float acc0 = xwrow[(size_t)t * HGH];
        float acc1 = 0.0f, acc2 = 0.0f, acc3 = 0.0f;
        float4 w[8];
        #pragma unroll
        for (int i = 0; i < 8; i++) w[i] = Wp[(i << 8) + j];
        #pragma unroll 1
        for (int g = 0; g < 8; g++) {
            float4 wn[8];
            if (g < 7) {
                #pragma unroll
                for (int i = 0; i < 8; i++) wn[i] = Wp[((((g + 1) << 3) + i) << 8) + j];
            }
            #pragma unroll
            for (int i = 0; i < 8; i++) {
                float4 h = hs4[cur][(g << 3) + i];
                acc0 = fmaf(w[i].x, h.x, acc0);
                acc1 = fmaf(w[i].y, h.y, acc1);
                acc2 = fmaf(w[i].z, h.z, acc2);
                acc3 = fmaf(w[i].w, h.w, acc3);
            }
            #pragma unroll
            for (int i = 0; i < 8; i++) w[i] = wn[i];
        }
        float hn = tanhf((acc0 + acc1) + (acc2 + acc3));
        ((float*)hs4[cur ^ 1])[j] = hn;
        float o = hn;
        if (applyMask && t > 0) o *= (float)mask[b*SS0 + (t - 1)];
        Hout[(size_t)(b*SS + t) * HGH + j] = o;
        cur ^= 1;
        __syncthreads();
    }
}

// ---------------- generic tiled SIMT GEMM (input proj + tags) ----------------
__device__ __forceinline__ void gemm_tile_loop(const float* __restrict__ A,
                                               const float* __restrict__ B,
                                               int K, int J, int n0, int j0, int tid,
                                               float acc[4][4],
                                               float (*As)[64], float (*Bs)[64])
{
    int tx = tid & 15, ty = tid >> 4;
    for (int k0 = 0; k0 < K; k0 += 16) {
        __syncthreads();
        {
            int row = tid >> 2;
            int kb  = (tid & 3) << 2;
            float4 av = *(const float4*)&A[(size_t)(n0 + row) * K + k0 + kb];
            As[kb + 0][row] = av.x;
            As[kb + 1][row] = av.y;
            As[kb + 2][row] = av.z;
            As[kb + 3][row] = av.w;
        }
        {
            int row = tid >> 4;
            int cb  = (tid & 15) << 2;
            *(float4*)&Bs[row][cb] = *(const float4*)&B[(size_t)(k0 + row) * J + j0 + cb];
        }
        __syncthreads();
        #pragma unroll
        for (int kk = 0; kk < 16; kk++) {
            float4 a = *(const float4*)&As[kk][ty << 2];
            float4 b = *(const float4*)&Bs[kk][tx << 2];
            acc[0][0] = fmaf(a.x, b.x, acc[0][0]);
            acc[0][1] = fmaf(a.x, b.y, acc[0][1]);
            acc[0][2] = fmaf(a.x, b.z, acc[0][2]);
            acc[0][3] = fmaf(a.x, b.w, acc[0][3]);
            acc[1][0] = fmaf(a.y, b.x, acc[1][0]);
            acc[1][1] = fmaf(a.y, b.y, acc[1][1]);
            acc[1][2] = fmaf(a.y, b.z, acc[1][2]);
            acc[1][3] = fmaf(a.y, b.w, acc[1][3]);
            acc[2][0] = fmaf(a.z, b.x, acc[2][0]);
            acc[2][1] = fmaf(a.z, b.y, acc[2][1]);
            acc[2][2] = fmaf(a.z, b.z, acc[2][2]);
            acc[2][3] = fmaf(a.z, b.w, acc[2][3]);
            acc[3][0] = fmaf(a.w, b.x, acc[3][0]);
            acc[3][1] = fmaf(a.w, b.y, acc[3][1]);
            acc[3][2] = fmaf(a.w, b.z, acc[3][2]);
            acc[3][3] = fmaf(a.w, b.w, acc[3][3]);
        }
    }
}

// EPI: 0 = +b1+b2 ; 1 = elu(+b1)
template<int EPI>
__global__ void __launch_bounds__(256) gemm_kernel(const float* __restrict__ A,
                                                   const float* __restrict__ B,
                                                   const float* __restrict__ b1,
                                                   const float* __restrict__ b2,
                                                   float* __restrict__ C,
                                                   int K, int J)
{
    __shared__ float As[16][64];
    __shared__ float Bs[16][64];
    int tid = threadIdx.x;
    int n0 = blockIdx.x * 64;
    int j0 = blockIdx.y * 64;
    float acc[4][4] = {};
    gemm_tile_loop(A, B, K, J, n0, j0, tid, acc, As, Bs);

    int tx = tid & 15, ty = tid >> 4;
    int j_base = j0 + (tx << 2);
    #pragma unroll
    for (int i = 0; i < 4; i++) {
        int n = n0 + (ty << 2) + i;
        float r[4];
        #pragma unroll
        for (int l = 0; l < 4; l++) {
            int j = j_base + l;
            float x = acc[i][l];
            if (EPI == 0) {
                x += b1[j] + b2[j];
            } else {
                x += b1[j];
                x = (x > 0.0f) ? x : expm1f(x);
            }
            r[l] = x;
        }
        *(float4*)&C[(size_t)n * J + j_base] = make_float4(r[0], r[1], r[2], r[3]);
    }
}

// ---------------- fused edge scan (tf32 tensor cores, state resident in smem) ----
// Each CTA: 64 rows. 8 warps; warp tile 32x64 (2 m-tiles x 8 n-tiles of m16n8k8).
// Double-buffered B staging: LDG of chunk k+1 overlaps MMA of chunk k.

__device__ __forceinline__ void edge_gemm_accum(const float* __restrict__ As,  // smem state
                                                const float* __restrict__ Bg,  // global tf32 KxN
                                                float* __restrict__ Bs,
                                                float acc[2][8][4],
                                                int rg, int cg, int gid, int tig, int tid)
{
    float4 rbuf[8];
    #pragma unroll
    for (int i = 0; i < 8; i++) {
        int f = tid + i*256;
        int r = f >> 6, c4 = f & 63;
        rbuf[i] = *(const float4*)&Bg[(size_t)r*256 + (c4<<2)];
    }
    #pragma unroll 1
    for (int k0 = 0; k0 < 256; k0 += 32) {
        __syncthreads();    // previous consumers of Bs done
        #pragma unroll
        for (int i = 0; i < 8; i++) {
            int f = tid + i*256;
            int r = f >> 6, c4 = f & 63;
            *(float4*)&Bs[r*BST + (c4<<2)] = rbuf[i];
        }
        __syncthreads();    // Bs ready
        if (k0 < 224) {
            #pragma unroll
            for (int i = 0; i < 8; i++) {
                int f = tid + i*256;
                int r = f >> 6, c4 = f & 63;
                rbuf[i] = *(const float4*)&Bg[(size_t)(k0 + 32 + r)*256 + (c4<<2)];
            }
        }
        #pragma unroll
        for (int ks = 0; ks < 4; ks++) {
            int kk = ks*8;
            uint32_t a[2][4];
            #pragma unroll
            for (int mt = 0; mt < 2; mt++) {
                int row0 = rg*32 + mt*16 + gid;
                int kc = k0 + kk + tig;
                a[mt][0] = f2tf32(As[(size_t) row0   *HST + kc]);
                a[mt][1] = f2tf32(As[(size_t)(row0+8)*HST + kc]);
                a[mt][2] = f2tf32(As[(size_t) row0   *HST + kc+4]);
                a[mt][3] = f2tf32(As[(size_t)(row0+8)*HST + kc+4]);
            }
            #pragma unroll
            for (int nt = 0; nt < 8; nt++) {
                int col = cg*64 + nt*8 + gid;
                uint32_t b0 = __float_as_uint(Bs[(kk+tig)  *BST + col]);
                uint32_t b1 = __float_as_uint(Bs[(kk+tig+4)*BST + col]);
                #pragma unroll
                for (int mt = 0; mt < 2; mt++) {
                    mma_tf32(acc[mt][nt][0], acc[mt][nt][1], acc[mt][nt][2], acc[mt][nt][3],
                             a[mt][0], a[mt][1], a[mt][2], a[mt][3], b0, b1);
                }
            }
        }
    }
}

__global__ void __launch_bounds__(256, 1) edge_fused_kernel(
    const float* __restrict__ gs,
    const float* __restrict__ Whh0T,
    const float* __restrict__ Wih1T,
    const float* __restrict__ Whh1T,
    const float* __restrict__ w0,
    const float* __restrict__ bih0, const float* __restrict__ bhh0,
    const float* __restrict__ bih1, const float* __restrict__ bhh1,
    const float* __restrict__ clsW, const float* __restrict__ clsb,
    float* __restrict__ probs)
{
    extern __shared__ float sm[];
    float* h0s = sm;
    float* h1s = h0s + ROWS_PER_CTA*HST;
    float* ps  = h1s + ROWS_PER_CTA*HST;
    float* w0s = ps + ROWS_PER_CTA;
    float* bc0 = w0s + 256;
    float* bc1 = bc0 + 256;
    float* clw = bc1 + 256;
    float* Bs  = clw + 256;
    __shared__ float s_clsb;

    int tid = threadIdx.x;
    int lane = tid & 31, warp = tid >> 5;
    int gid = lane >> 2, tig = lane & 3;
    int rg = warp >> 2, cg = warp & 3;
    int n0 = blockIdx.x * ROWS_PER_CTA;

    // consts
    w0s[tid] = w0[tid];
    bc0[tid] = bih0[tid] + bhh0[tid];
    bc1[tid] = bih1[tid] + bhh1[tid];
    clw[tid] = clsW[tid];
    if (tid == 0) s_clsb = clsb[0];

    // init state: h0 = gs rows, h1 = 0, p = 1
    #pragma unroll
    for (int i = tid; i < ROWS_PER_CTA*256; i += 256) {
        int r = i >> 8, c = i & 255;
        h0s[r*HST + c] = gs[(size_t)(n0 + r)*256 + c];
        h1s[r*HST + c] = 0.0f;
    }
    if (tid < ROWS_PER_CTA) ps[tid] = 1.0f;
    __syncthreads();

    float acc[2][8][4];

    for (int m = 0; m < MM; m++) {
        // ---- h0_new = tanh(h0 @ Whh0^T + p*w0 + bc0) ----
        #pragma unroll
        for (int mt=0;mt<2;mt++)
            #pragma unroll
            for (int nt=0;nt<8;nt++)
                #pragma unroll
                for (int q=0;q<4;q++) acc[mt][nt][q] = 0.0f;

        edge_gemm_accum(h0s, Whh0T, Bs, acc, rg, cg, gid, tig, tid);

        __syncthreads();
        #pragma unroll
        for (int mt=0;mt<2;mt++) {
            #pragma unroll
            for (int nt=0;nt<8;nt++) {
                #pragma unroll
                for (int q=0;q<4;q++) {
                    int row = rg*32 + mt*16 + gid + ((q>>1)<<3);
                    int col = cg*64 + nt*8 + tig*2 + (q&1);
                    float x = acc[mt][nt][q] + ps[row]*w0s[col] + bc0[col];
                    h0s[row*HST + col] = fast_tanh(x);
                }
            }
        }
        __syncthreads();

        // ---- h1_new = tanh(h0_new @ Wih1^T + h1 @ Whh1^T + bc1) ----
        #pragma unroll
        for (int mt=0;mt<2;mt++)
            #pragma unroll
            for (int nt=0;nt<8;nt++)
                #pragma unroll
                for (int q=0;q<4;q++) acc[mt][nt][q] = 0.0f;

        edge_gemm_accum(h0s, Wih1T, Bs, acc, rg, cg, gid, tig, tid);
        edge_gemm_accum(h1s, Whh1T, Bs, acc, rg, cg, gid, tig, tid);

        __syncthreads();
        #pragma unroll
        for (int mt=0;mt<2;mt++) {
            #pragma unroll
            for (int nt=0;nt<8;nt++) {
                #pragma unroll
                for (int q=0;q<4;q++) {
                    int row = rg*32 + mt*16 + gid + ((q>>1)<<3);
                    int col = cg*64 + nt*8 + tig*2 + (q&1);
                    float x = acc[mt][nt][q] + bc1[col];
                    h1s[row*HST + col] = fast_tanh(x);
                }
            }
        }
        __syncthreads();

        // ---- p = sigmoid(h1 . clsW + clsb) ----
        #pragma unroll
        for (int i = 0; i < 8; i++) {
            int r = warp*8 + i;
            float s = 0.0f;
            #pragma unroll
            for (int c = lane; c < 256; c += 32)
                s = fmaf(h1s[r*HST + c], clw[c], s);
            #pragma unroll
            for (int o = 16; o; o >>= 1) s += __shfl_xor_sync(0xFFFFFFFFu, s, o);
            if (lane == 0) {
                float p = 1.0f / (1.0f + expf(-(s + s_clsb)));
                ps[r] = p;
                probs[(size_t)m*NN + n0 + r] = p;
            }
        }
        __syncthreads();
    }
}

// ---------------- arc_logits assembly ----------------
__global__ void arc_kernel(const float* __restrict__ probs, float* __restrict__ arc)
{
    int j = blockIdx.x;
    int b = blockIdx.y;
    int i = threadIdx.x;
    int start = (i - MM > 0) ? (i - MM) : 0;
    float v = 0.0f;
    if (j >= start && j < i) {
        int midx = j - start;
        v = probs[(size_t)midx * NN + b * SS + i];
    }
    arc[(size_t)(b * SS + j) * SS + i] = v;
}

// ---------------- host orchestration ----------------
static const int EDGE_SMEM_BYTES =
    (2*ROWS_PER_CTA*HST + ROWS_PER_CTA + 4*256 + 32*BST) * (int)sizeof(float);

extern "C" void kernel_launch(void* const* d_in, const int* in_sizes, int n_in,
                              void* d_out, int out_size)
{
    const float* input   = (const float*)d_in[0];
    const float* sentinel= (const float*)d_in[1];
    const float* g_Wih0  = (const float*)d_in[2];
    const float* g_Whh0  = (const float*)d_in[3];
    const float* g_bih0  = (const float*)d_in[4];
    const float* g_bhh0  = (const float*)d_in[5];
    const float* g_Wih1  = (const float*)d_in[6];
    const float* g_Whh1  = (const float*)d_in[7];
    const float* g_bih1  = (const float*)d_in[8];
    const float* g_bhh1  = (const float*)d_in[9];
    const float* e_Wih0  = (const float*)d_in[10];
    const float* e_Whh0  = (const float*)d_in[11];
    const float* e_bih0  = (const float*)d_in[12];
    const float* e_bhh0  = (const float*)d_in[13];
    const float* e_Wih1  = (const float*)d_in[14];
    const float* e_Whh1  = (const float*)d_in[15];
    const float* e_bih1  = (const float*)d_in[16];
    const float* e_bhh1  = (const float*)d_in[17];
    const float* cls_W   = (const float*)d_in[18];
    const float* cls_b   = (const float*)d_in[19];
    const float* head_W  = (const float*)d_in[20];
    const float* head_b  = (const float*)d_in[21];
    const float* dep_W   = (const float*)d_in[22];
    const float* dep_b   = (const float*)d_in[23];
    const int*   mask    = (const int*)  d_in[24];
    (void)in_sizes; (void)n_in; (void)out_size;

    float* out = (float*)d_out;
    float* out_head = out;
    float* out_dep  = out + (size_t)NN * TT;
    float* out_arc  = out + (size_t)2 * NN * TT;

    float *pX, *pXW, *pH0, *pGS, *pprobs;
    float *pWTih0g, *pWTih1g, *pWThh0e, *pWTih1e, *pWThh1e, *pWThead, *pWTdep;
    float4 *pWp0, *pWp1;
    cudaGetSymbolAddress((void**)&pX, d_X);
    cudaGetSymbolAddress((void**)&pXW, d_XW);
    cudaGetSymbolAddress((void**)&pH0, d_H0);
    cudaGetSymbolAddress((void**)&pGS, d_GS);
    cudaGetSymbolAddress((void**)&pprobs, d_probs);
    cudaGetSymbolAddress((void**)&pWTih0g, d_WT_ih0g);
    cudaGetSymbolAddress((void**)&pWTih1g, d_WT_ih1g);
    cudaGetSymbolAddress((void**)&pWp0, d_Wp0);
    cudaGetSymbolAddress((void**)&pWp1, d_Wp1);
    cudaGetSymbolAddress((void**)&pWThh0e, d_WT_hh0e);
    cudaGetSymbolAddress((void**)&pWTih1e, d_WT_ih1e);
    cudaGetSymbolAddress((void**)&pWThh1e, d_WT_hh1e);
    cudaGetSymbolAddress((void**)&pWThead, d_WT_head);
    cudaGetSymbolAddress((void**)&pWTdep, d_WT_dep);

    cudaFuncSetAttribute(edge_fused_kernel,
                         cudaFuncAttributeMaxDynamicSharedMemorySize, EDGE_SMEM_BYTES);

    // launch 1: fused prep (build X, 7 transposes, 2 packs)
    prep_kernel<<<dim3(4096, 10), 256>>>(
        input, sentinel, g_Wih0, g_Wih1, e_Whh0, e_Wih1, e_Whh1, head_W, dep_W,
        g_Whh0, g_Whh1,
        pX, pWTih0g, pWTih1g, pWThh0e, pWTih1e, pWThh1e, pWThead, pWTdep,
        pWp0, pWp1);

    // launch 2-3: g-RNN layer 0
    gemm_kernel<0><<<dim3(NN/64, HGH/64), 256>>>(pX, pWTih0g, g_bih0, g_bhh0, pXW, DD, HGH);
    scan_g_kernel<<<BB, 256>>>(pXW, pWp0, pH0, nullptr, 0);

    // launch 4-5: g-RNN layer 1 (mask applied on output)
    gemm_kernel<0><<<dim3(NN/64, HGH/64), 256>>>(pH0, pWTih1g, g_bih1, g_bhh1, pXW, HGH, HGH);
    scan_g_kernel<<<BB, 256>>>(pXW, pWp1, pGS, mask, 1);

    // launch 6 (ncu captures this one): fused edge scan
    edge_fused_kernel<<<NN/ROWS_PER_CTA, 256, EDGE_SMEM_BYTES>>>(
        pGS, pWThh0e, pWTih1e, pWThh1e,
        e_Wih0, e_bih0, e_bhh0, e_bih1, e_bhh1,
        cls_W, cls_b, pprobs);

    // tags (only need GS; placed after edge so edge is launch #6)
    gemm_kernel<1><<<dim3(NN/64, TT/64), 256>>>(pGS, pWThead, head_b, nullptr, out_head, HGH, TT);
    gemm_kernel<1><<<dim3(NN/64, TT/64), 256>>>(pGS, pWTdep,  dep_b,  nullptr, out_dep,  HGH, TT);

    // arc_logits
    arc_kernel<<<dim3(SS, BB), SS>>>(pprobs, out_arc);
}

// round 5
// speedup vs baseline: 3.6120x; 1.2862x over previous
#include <cuda_runtime.h>
#include <cuda_bf16.h>
#include <math.h>
#include <stdint.h>

// Problem constants
#define BB   16
#define SS   512
#define SS0  511
#define DD   512
#define HGH  256
#define HEH  256
#define TT   128
#define MM   32
#define NN   (BB*SS)   // 8192

#define ROWS_PER_CTA 64
#define AST  132      // edge state stride (uint32 bf16x2 units)
#define BSTE 264      // edge B buffer stride (uint32 bf16x2 units)

// ---------------- device scratch ----------------
__device__ float  d_X   [NN*DD];
__device__ float  d_XW  [NN*HGH];
__device__ float  d_H0  [NN*HGH];
__device__ float  d_GS  [NN*HGH];
__device__ float  d_probs[MM*NN];

__device__ float    d_WT_ih0g[DD*HGH];
__device__ float    d_WT_ih1g[HGH*HGH];
__device__ float4   d_Wp0[(HGH/4)*HGH];
__device__ float4   d_Wp1[(HGH/4)*HGH];
__device__ uint32_t d_Bpk[3*128*256];    // bf16x2-packed e-weights, K-major pairs
__device__ float    d_WT_head[HGH*TT];
__device__ float    d_WT_dep [HGH*TT];

// ---------------- helpers ----------------
__device__ __forceinline__ float fast_tanh(float x) {
    float y;
    asm("tanh.approx.f32 %0, %1;" : "=f"(y) : "f"(x));
    return y;
}

__device__ __forceinline__ unsigned long long fmaf32x2(unsigned long long a,
                                                       unsigned long long b,
                                                       unsigned long long c) {
    unsigned long long d;
    asm("fma.rn.f32x2 %0, %1, %2, %3;" : "=l"(d) : "l"(a), "l"(b), "l"(c));
    return d;
}

__device__ __forceinline__ float2 unpack_f32x2(unsigned long long v) {
    float lo, hi;
    asm("mov.b64 {%0,%1}, %2;" : "=f"(lo), "=f"(hi) : "l"(v));
    return make_float2(lo, hi);
}

__device__ __forceinline__ void mma_bf16(float c[4], const uint32_t a[4],
                                         uint32_t b0, uint32_t b1) {
    asm volatile("mma.sync.aligned.m16n8k16.row.col.f32.bf16.bf16.f32 "
        "{%0,%1,%2,%3},{%4,%5,%6,%7},{%8,%9},{%0,%1,%2,%3};"
        : "+f"(c[0]), "+f"(c[1]), "+f"(c[2]), "+f"(c[3])
        : "r"(a[0]), "r"(a[1]), "r"(a[2]), "r"(a[3]), "r"(b0), "r"(b1));
}

__device__ __forceinline__ uint32_t pack_bf16x2(float lo, float hi) {
    __nv_bfloat162 v = __floats2bfloat162_rn(lo, hi);
    return *reinterpret_cast<uint32_t*>(&v);
}

// ---------------- single fused prep kernel ----------------
// task 0: build X (4096 blocks); 1: g_Wih0^T; 2: g_Wih1^T; 3: head^T; 4: dep^T;
// 5,6: pack g_Whh; 7,8,9: pack e-weights to bf16x2 pairs
__device__ __forceinline__ void prep_transpose(const float* __restrict__ in,
                                               float* __restrict__ out,
                                               int R, int C, int bx, int tid)
{
    int tilesC = C >> 5, tilesR = R >> 5;
    if (bx >= tilesC * tilesR) return;
    int c0 = (bx % tilesC) << 5;
    int r0 = (bx / tilesC) << 5;
    __shared__ float tile[32][33];
    int x = tid & 31, y = tid >> 5;
    #pragma unroll
    for (int dy = 0; dy < 32; dy += 8)
        tile[y + dy][x] = in[(size_t)(r0 + y + dy) * C + c0 + x];
    __syncthreads();
    #pragma unroll
    for (int dy = 0; dy < 32; dy += 8)
        out[(size_t)(c0 + y + dy) * R + r0 + x] = tile[x][y + dy];
}

__global__ void __launch_bounds__(256) prep_kernel(
    const float* __restrict__ input, const float* __restrict__ sent,
    const float* __restrict__ g_Wih0, const float* __restrict__ g_Wih1,
    const float* __restrict__ head_W, const float* __restrict__ dep_W,
    const float* __restrict__ g_Whh0, const float* __restrict__ g_Whh1,
    const float* __restrict__ e_Whh0, const float* __restrict__ e_Wih1,
    const float* __restrict__ e_Whh1,
    float* __restrict__ X,
    float* __restrict__ WTih0g, float* __restrict__ WTih1g,
    float* __restrict__ WThead, float* __restrict__ WTdep,
    float4* __restrict__ Wp0, float4* __restrict__ Wp1,
    uint32_t* __restrict__ Bpk)
{
    int task = blockIdx.y;
    int bx   = blockIdx.x;
    int tid  = threadIdx.x;
    if (task == 0) {
        int idx = bx * 256 + tid;
        int n  = idx >> 7;
        int k4 = idx & 127;
        int b = n >> 9, s = n & 511;
        float4 v;
        if (s == 0) v = ((const float4*)sent)[k4];
        else        v = ((const float4*)input)[(size_t)((b*SS0 + s - 1) << 7) + k4];
        ((float4*)X)[idx] = v;
    } else if (task == 1) {
        prep_transpose(g_Wih0, WTih0g, HGH, DD, bx, tid);
    } else if (task == 2) {
        prep_transpose(g_Wih1, WTih1g, HGH, HGH, bx, tid);
    } else if (task == 3) {
        prep_transpose(head_W, WThead, TT, HGH, bx, tid);
    } else if (task == 4) {
        prep_transpose(dep_W, WTdep, TT, HGH, bx, tid);
    } else if (task == 5 || task == 6) {
        if (bx >= 64) return;
        const float* W = (task == 5) ? g_Whh0 : g_Whh1;
        float4* Wp = (task == 5) ? Wp0 : Wp1;
        int idx = bx * 256 + tid;
        int k4 = idx >> 8, j = idx & 255;
        const float* src = W + (size_t)j * HGH + (k4 << 2);
        Wp[idx] = make_float4(src[0], src[1], src[2], src[3]);
    } else {
        // pack e-weight W (N=256 x K=256, row-major) into [k2][n] bf16x2
        if (bx >= 128) return;
        int seg = task - 7;                       // 0: Whh0, 1: Wih1, 2: Whh1
        const float* W = (seg == 0) ? e_Whh0 : (seg == 1) ? e_Wih1 : e_Whh1;
        uint32_t* out = Bpk + seg * 128 * 256;
        int idx = bx * 256 + tid;
        int k2 = idx >> 8, n = idx & 255;
        float2 v = *(const float2*)&W[(size_t)n * 256 + (k2 << 1)];
        out[k2 * 256 + n] = pack_bf16x2(v.x, v.y);
    }
}

// ---------------- g-RNN recurrence: one CTA per batch, f32x2 FMA ----------------
__global__ void __launch_bounds__(256, 1) scan_g_kernel(const float* __restrict__ XW,
                                                        const float4* __restrict__ Wp,
                                                        float* __restrict__ Hout,
                                                        const int* __restrict__ mask,
                                                        int applyMask)
{
    int b = blockIdx.x;
    int j = threadIdx.x;
    __shared__ ulonglong2 hsq[2][HGH/4];   // same layout as float4 h
    ((float*)hsq[0])[j] = 0.0f;
    __syncthreads();
    int cur = 0;
    const float* xwrow = XW + (size_t)b * SS * HGH + j;
    const ulonglong2* Wq = reinterpret_cast<const ulonglong2*>(Wp);

    for (int t = 0; t < SS; t++) {
        float xw = xwrow[(size_t)t * HGH];
        unsigned long long accA = (unsigned long long)__float_as_uint(xw); // (xw, 0)
        unsigned long long accB = 0ull;

        ulonglong2 w[3][8];
        #pragma unroll
        for (int i = 0; i < 8; i++) w[0][i] = Wq[(0*8 + i) * 256 + j];
        #pragma unroll
        for (int i = 0; i < 8; i++) w[1][i] = Wq[(1*8 + i) * 256 + j];
        #pragma unroll
        for (int i = 0; i < 8; i++) w[2][i] = Wq[(2*8 + i) * 256 + j];

        #pragma unroll
        for (int g = 0; g < 8; g++) {
            const int nb = g % 3;
            #pragma unroll
            for (int i = 0; i < 8; i++) {
                ulonglong2 h = hsq[cur][(g << 3) + i];
                accA = fmaf32x2(w[nb][i].x, h.x, accA);
                accB = fmaf32x2(w[nb][i].y, h.y, accB);
            }
            if (g + 3 < 8) {
                #pragma unroll
                for (int i = 0; i < 8; i++)
                    w[nb][i] = Wq[(((g + 3) << 3) + i) * 256 + j];
            }
        }
        float2 a = unpack_f32x2(accA);
        float2 bsum = unpack_f32x2(accB);
        float hn = fast_tanh((a.x + a.y) + (bsum.x + bsum.y));
        ((float*)hsq[cur ^ 1])[j] = hn;
        float o = hn;
        if (applyMask && t > 0) o *= (float)mask[b*SS0 + (t - 1)];
        Hout[(size_t)(b*SS + t) * HGH + j] = o;
        cur ^= 1;
        __syncthreads();
    }
}

// ---------------- generic tiled SIMT GEMM (input proj + tags) ----------------
__device__ __forceinline__ void gemm_tile_loop(const float* __restrict__ A,
                                               const float* __restrict__ B,
                                               int K, int J, int n0, int j0, int tid,
                                               float acc[4][4],
                                               float (*As)[64], float (*Bs)[64])
{
    int tx = tid & 15, ty = tid >> 4;
    for (int k0 = 0; k0 < K; k0 += 16) {
        __syncthreads();
        {
            int row = tid >> 2;
            int kb  = (tid & 3) << 2;
            float4 av = *(const float4*)&A[(size_t)(n0 + row) * K + k0 + kb];
            As[kb + 0][row] = av.x;
            As[kb + 1][row] = av.y;
            As[kb + 2][row] = av.z;
            As[kb + 3][row] = av.w;
        }
        {
            int row = tid >> 4;
            int cb  = (tid & 15) << 2;
            *(float4*)&Bs[row][cb] = *(const float4*)&B[(size_t)(k0 + row) * J + j0 + cb];
        }
        __syncthreads();
        #pragma unroll
        for (int kk = 0; kk < 16; kk++) {
            float4 a = *(const float4*)&As[kk][ty << 2];
            float4 b = *(const float4*)&Bs[kk][tx << 2];
            acc[0][0] = fmaf(a.x, b.x, acc[0][0]);
            acc[0][1] = fmaf(a.x, b.y, acc[0][1]);
            acc[0][2] = fmaf(a.x, b.z, acc[0][2]);
            acc[0][3] = fmaf(a.x, b.w, acc[0][3]);
            acc[1][0] = fmaf(a.y, b.x, acc[1][0]);
            acc[1][1] = fmaf(a.y, b.y, acc[1][1]);
            acc[1][2] = fmaf(a.y, b.z, acc[1][2]);
            acc[1][3] = fmaf(a.y, b.w, acc[1][3]);
            acc[2][0] = fmaf(a.z, b.x, acc[2][0]);
            acc[2][1] = fmaf(a.z, b.y, acc[2][1]);
            acc[2][2] = fmaf(a.z, b.z, acc[2][2]);
            acc[2][3] = fmaf(a.z, b.w, acc[2][3]);
            acc[3][0] = fmaf(a.w, b.x, acc[3][0]);
            acc[3][1] = fmaf(a.w, b.y, acc[3][1]);
            acc[3][2] = fmaf(a.w, b.z, acc[3][2]);
            acc[3][3] = fmaf(a.w, b.w, acc[3][3]);
        }
    }
}

// EPI: 0 = +b1+b2 ; 1 = elu(+b1)
template<int EPI>
__global__ void __launch_bounds__(256) gemm_kernel(const float* __restrict__ A,
                                                   const float* __restrict__ B,
                                                   const float* __restrict__ b1,
                                                   const float* __restrict__ b2,
                                                   float* __restrict__ C,
                                                   int K, int J)
{
    __shared__ float As[16][64];
    __shared__ float Bs[16][64];
    int tid = threadIdx.x;
    int n0 = blockIdx.x * 64;
    int j0 = blockIdx.y * 64;
    float acc[4][4] = {};
    gemm_tile_loop(A, B, K, J, n0, j0, tid, acc, As, Bs);

    int tx = tid & 15, ty = tid >> 4;
    int j_base = j0 + (tx << 2);
    #pragma unroll
    for (int i = 0; i < 4; i++) {
        int n = n0 + (ty << 2) + i;
        float r[4];
        #pragma unroll
        for (int l = 0; l < 4; l++) {
            int j = j_base + l;
            float x = acc[i][l];
            if (EPI == 0) {
                x += b1[j] + b2[j];
            } else {
                x += b1[j];
                x = (x > 0.0f) ? x : expm1f(x);
            }
            r[l] = x;
        }
        *(float4*)&C[(size_t)n * J + j_base] = make_float4(r[0], r[1], r[2], r[3]);
    }
}

// ---------------- fused edge scan: bf16 MMA, cp.async 3-buffer pipeline ----------
__device__ __forceinline__ void edge_cp_chunk(uint32_t* Bs, int nb,
                                              const uint32_t* src, int tid)
{
    uint32_t dstb = (uint32_t)__cvta_generic_to_shared(Bs + nb * 32 * BSTE);
    #pragma unroll
    for (int i = 0; i < 8; i++) {
        int f = tid + (i << 8);
        int r = f >> 6, c4 = f & 63;
        uint32_t d = dstb + (uint32_t)(r * BSTE + (c4 << 2)) * 4u;
        asm volatile("cp.async.cg.shared.global [%0], [%1], 16;"
                     :: "r"(d), "l"(src + r * 256 + (c4 << 2)));
    }
    asm volatile("cp.async.commit_group;");
}

// One GEMM pass over (up to) two segments: chunks of K=64 (32 k2-rows).
__device__ __forceinline__ void edge_pass(
    const uint32_t* __restrict__ hA0, const uint32_t* __restrict__ Bg0, int n0ch,
    const uint32_t* __restrict__ hA1, const uint32_t* __restrict__ Bg1, int n1ch,
    uint32_t* __restrict__ Bs, float acc[2][8][4],
    int rg, int cg, int gid, int tig, int tid)
{
    int nch = n0ch + n1ch;
    // preload chunks 0,1
    edge_cp_chunk(Bs, 0, (0 < n0ch) ? Bg0 : Bg1, tid);
    edge_cp_chunk(Bs, 1, (1 < n0ch) ? (Bg0 + 32*256) : (Bg1 + (1 - n0ch) * 32*256), tid);

    for (int c = 0; c < nch; c++) {
        if (c + 1 < nch) asm volatile("cp.async.wait_group 1;");
        else             asm volatile("cp.async.wait_group 0;");
        __syncthreads();

        const uint32_t* hA = (c < n0ch) ? hA0 : hA1;
        int aBase = ((c < n0ch) ? c : (c - n0ch)) * 32;
        const uint32_t* Bb = Bs + (c % 3) * 32 * BSTE;

        #pragma unroll
        for (int ks = 0; ks < 4; ks++) {
            uint32_t a[2][4];
            #pragma unroll
            for (int mt = 0; mt < 2; mt++) {
                int r0 = rg*32 + mt*16 + gid;
                int kb = aBase + ks*8 + tig;
                a[mt][0] = hA[r0*AST + kb];
                a[mt][1] = hA[(r0+8)*AST + kb];
                a[mt][2] = hA[r0*AST + kb + 4];
                a[mt][3] = hA[(r0+8)*AST + kb + 4];
            }
            #pragma unroll
            for (int nt = 0; nt < 8; nt++) {
                int col = cg*64 + nt*8 + gid;
                uint32_t b0 = Bb[(ks*8 + tig)*BSTE + col];
                uint32_t b1 = Bb[(ks*8 + tig + 4)*BSTE + col];
                mma_bf16(acc[0][nt], a[0], b0, b1);
                mma_bf16(acc[1][nt], a[1], b0, b1);
            }
        }
        int cn = c + 2;
        if (cn < nch) {
            const uint32_t* s = (cn < n0ch) ? (Bg0 + cn * 32*256)
                                            : (Bg1 + (cn - n0ch) * 32*256);
            edge_cp_chunk(Bs, cn % 3, s, tid);
        }
    }
}

__global__ void __launch_bounds__(256, 1) edge_fused_kernel(
    const float* __restrict__ gs,
    const uint32_t* __restrict__ Bpk,       // [3][128*256]
    const float* __restrict__ w0,
    const float* __restrict__ bih0, const float* __restrict__ bhh0,
    const float* __restrict__ bih1, const float* __restrict__ bhh1,
    const float* __restrict__ clsW, const float* __restrict__ clsb,
    float* __restrict__ probs)
{
    extern __shared__ uint32_t smu[];
    uint32_t* hs0 = smu;                         // 64*AST
    uint32_t* hs1 = hs0 + ROWS_PER_CTA*AST;
    uint32_t* Bs  = hs1 + ROWS_PER_CTA*AST;      // 3 * 32 * BSTE
    float* fsm = (float*)(Bs + 3*32*BSTE);
    float* ps  = fsm;          // 64
    float* w0s = ps + 64;      // 256
    float* bc0 = w0s + 256;
    float* bc1 = bc0 + 256;
    float* clw = bc1 + 256;
    __shared__ float s_clsb;

    int tid = threadIdx.x;
    int lane = tid & 31, warp = tid >> 5;
    int gid = lane >> 2, tig = lane & 3;
    int rg = warp >> 2, cg = warp & 3;
    int n0 = blockIdx.x * ROWS_PER_CTA;

    const uint32_t* B0 = Bpk;
    const uint32_t* B1 = Bpk + 128*256;
    const uint32_t* B2 = Bpk + 2*128*256;

    w0s[tid] = w0[tid];
    bc0[tid] = bih0[tid] + bhh0[tid];
    bc1[tid] = bih1[tid] + bhh1[tid];
    clw[tid] = clsW[tid];
    if (tid == 0) s_clsb = clsb[0];

    // init: h0 = bf16(gs rows), h1 = 0, p = 1
    for (int i = tid; i < ROWS_PER_CTA*128; i += 256) {
        int r = i >> 7, c2 = i & 127;
        float2 v = *(const float2*)&gs[(size_t)(n0 + r)*256 + (c2 << 1)];
        hs0[r*AST + c2] = pack_bf16x2(v.x, v.y);
        hs1[r*AST + c2] = 0u;
    }
    if (tid < ROWS_PER_CTA) ps[tid] = 1.0f;
    __syncthreads();

    float acc[2][8][4];

    for (int m = 0; m < MM; m++) {
        // ---- pass 1: acc = h0 @ Whh0^T ----
        #pragma unroll
        for (int mt = 0; mt < 2; mt++)
            #pragma unroll
            for (int nt = 0; nt < 8; nt++)
                #pragma unroll
                for (int q = 0; q < 4; q++) acc[mt][nt][q] = 0.0f;

        edge_pass(hs0, B0, 4, hs0, B0, 0, Bs, acc, rg, cg, gid, tig, tid);
        __syncthreads();

        // epi1: h0 = tanh(acc + p*w0 + bc0), stored bf16x2
        #pragma unroll
        for (int mt = 0; mt < 2; mt++) {
            int r0 = rg*32 + mt*16 + gid;
            int r1 = r0 + 8;
            float p0 = ps[r0], p1 = ps[r1];
            #pragma unroll
            for (int nt = 0; nt < 8; nt++) {
                int cbase = cg*64 + nt*8 + tig*2;
                float x0 = acc[mt][nt][0] + p0*w0s[cbase]   + bc0[cbase];
                float x1 = acc[mt][nt][1] + p0*w0s[cbase+1] + bc0[cbase+1];
                float x2 = acc[mt][nt][2] + p1*w0s[cbase]   + bc0[cbase];
                float x3 = acc[mt][nt][3] + p1*w0s[cbase+1] + bc0[cbase+1];
                hs0[r0*AST + (cbase >> 1)] = pack_bf16x2(fast_tanh(x0), fast_tanh(x1));
                hs0[r1*AST + (cbase >> 1)] = pack_bf16x2(fast_tanh(x2), fast_tanh(x3));
            }
        }
        __syncthreads();

        // ---- pass 2 (merged): acc = h0_new @ Wih1^T + h1 @ Whh1^T ----
        #pragma unroll
        for (int mt = 0; mt < 2; mt++)
            #pragma unroll
            for (int nt = 0; nt < 8; nt++)
                #pragma unroll
                for (int q = 0; q < 4; q++) acc[mt][nt][q] = 0.0f;

        edge_pass(hs0, B1, 4, hs1, B2, 4, Bs, acc, rg, cg, gid, tig, tid);
        __syncthreads();

        // epi2: h1 = tanh(acc + bc1)
        #pragma unroll
        for (int mt = 0; mt < 2; mt++) {
            int r0 = rg*32 + mt*16 + gid;
            int r1 = r0 + 8;
            #pragma unroll
            for (int nt = 0; nt < 8; nt++) {
                int cbase = cg*64 + nt*8 + tig*2;
                float x0 = acc[mt][nt][0] + bc1[cbase];
                float x1 = acc[mt][nt][1] + bc1[cbase+1];
                float x2 = acc[mt][nt][2] + bc1[cbase];
                float x3 = acc[mt][nt][3] + bc1[cbase+1];
                hs1[r0*AST + (cbase >> 1)] = pack_bf16x2(fast_tanh(x0), fast_tanh(x1));
                hs1[r1*AST + (cbase >> 1)] = pack_bf16x2(fast_tanh(x2), fast_tanh(x3));
            }
        }
        __syncthreads();

        // ---- p = sigmoid(h1 . clsW + clsb) ----
        #pragma unroll
        for (int i = 0; i < 8; i++) {
            int r = warp*8 + i;
            float s = 0.0f;
            #pragma unroll
            for (int k = 0; k < 4; k++) {
                int c2 = lane + k*32;
                __nv_bfloat162 bv = *reinterpret_cast<const __nv_bfloat162*>(&hs1[r*AST + c2]);
                float2 fv = __bfloat1622float2(bv);
                s = fmaf(fv.x, clw[c2*2], fmaf(fv.y, clw[c2*2 + 1], s));
            }
            #pragma unroll
            for (int o = 16; o; o >>= 1) s += __shfl_xor_sync(0xFFFFFFFFu, s, o);
            if (lane == 0) {
                float p = 1.0f / (1.0f + expf(-(s + s_clsb)));
                ps[r] = p;
                probs[(size_t)m*NN + n0 + r] = p;
            }
        }
        __syncthreads();
    }
}

// ---------------- arc_logits assembly ----------------
__global__ void arc_kernel(const float* __restrict__ probs, float* __restrict__ arc)
{
    int j = blockIdx.x;
    int b = blockIdx.y;
    int i = threadIdx.x;
    int start = (i - MM > 0) ? (i - MM) : 0;
    float v = 0.0f;
    if (j >= start && j < i) {
        int midx = j - start;
        v = probs[(size_t)midx * NN + b * SS + i];
    }
    arc[(size_t)(b * SS + j) * SS + i] = v;
}

// ---------------- host orchestration ----------------
static const int EDGE_SMEM_BYTES =
    (2*ROWS_PER_CTA*AST + 3*32*BSTE) * 4 + (64 + 4*256) * 4;

extern "C" void kernel_launch(void* const* d_in, const int* in_sizes, int n_in,
                              void* d_out, int out_size)
{
    const float* input   = (const float*)d_in[0];
    const float* sentinel= (const float*)d_in[1];
    const float* g_Wih0  = (const float*)d_in[2];
    const float* g_Whh0  = (const float*)d_in[3];
    const float* g_bih0  = (const float*)d_in[4];
    const float* g_bhh0  = (const float*)d_in[5];
    const float* g_Wih1  = (const float*)d_in[6];
    const float* g_Whh1  = (const float*)d_in[7];
    const float* g_bih1  = (const float*)d_in[8];
    const float* g_bhh1  = (const float*)d_in[9];
    const float* e_Wih0  = (const float*)d_in[10];
    const float* e_Whh0  = (const float*)d_in[11];
    const float* e_bih0  = (const float*)d_in[12];
    const float* e_bhh0  = (const float*)d_in[13];
    const float* e_Wih1  = (const float*)d_in[14];
    const float* e_Whh1  = (const float*)d_in[15];
    const float* e_bih1  = (const float*)d_in[16];
    const float* e_bhh1  = (const float*)d_in[17];
    const float* cls_W   = (const float*)d_in[18];
    const float* cls_b   = (const float*)d_in[19];
    const float* head_W  = (const float*)d_in[20];
    const float* head_b  = (const float*)d_in[21];
    const float* dep_W   = (const float*)d_in[22];
    const float* dep_b   = (const float*)d_in[23];
    const int*   mask    = (const int*)  d_in[24];
    (void)in_sizes; (void)n_in; (void)out_size;

    float* out = (float*)d_out;
    float* out_head = out;
    float* out_dep  = out + (size_t)NN * TT;
    float* out_arc  = out + (size_t)2 * NN * TT;

    float *pX, *pXW, *pH0, *pGS, *pprobs;
    float *pWTih0g, *pWTih1g, *pWThead, *pWTdep;
    float4 *pWp0, *pWp1;
    uint32_t *pBpk;
    cudaGetSymbolAddress((void**)&pX, d_X);
    cudaGetSymbolAddress((void**)&pXW, d_XW);
    cudaGetSymbolAddress((void**)&pH0, d_H0);
    cudaGetSymbolAddress((void**)&pGS, d_GS);
    cudaGetSymbolAddress((void**)&pprobs, d_probs);
    cudaGetSymbolAddress((void**)&pWTih0g, d_WT_ih0g);
    cudaGetSymbolAddress((void**)&pWTih1g, d_WT_ih1g);
    cudaGetSymbolAddress((void**)&pWp0, d_Wp0);
    cudaGetSymbolAddress((void**)&pWp1, d_Wp1);
    cudaGetSymbolAddress((void**)&pWThead, d_WT_head);
    cudaGetSymbolAddress((void**)&pWTdep, d_WT_dep);
    cudaGetSymbolAddress((void**)&pBpk, d_Bpk);

    cudaFuncSetAttribute(edge_fused_kernel,
                         cudaFuncAttributeMaxDynamicSharedMemorySize, EDGE_SMEM_BYTES);

    // launch 1: fused prep
    prep_kernel<<<dim3(4096, 10), 256>>>(
        input, sentinel, g_Wih0, g_Wih1, head_W, dep_W, g_Whh0, g_Whh1,
        e_Whh0, e_Wih1, e_Whh1,
        pX, pWTih0g, pWTih1g, pWThead, pWTdep, pWp0, pWp1, pBpk);

    // launches 2-5: g-RNN layers
    gemm_kernel<0><<<dim3(NN/64, HGH/64), 256>>>(pX, pWTih0g, g_bih0, g_bhh0, pXW, DD, HGH);
    scan_g_kernel<<<BB, 256>>>(pXW, pWp0, pH0, nullptr, 0);
    gemm_kernel<0><<<dim3(NN/64, HGH/64), 256>>>(pH0, pWTih1g, g_bih1, g_bhh1, pXW, HGH, HGH);
    scan_g_kernel<<<BB, 256>>>(pXW, pWp1, pGS, mask, 1);

    // launch 6: fused edge scan (bf16 tensor cores)
    edge_fused_kernel<<<NN/ROWS_PER_CTA, 256, EDGE_SMEM_BYTES>>>(
        pGS, pBpk, e_Wih0, e_bih0, e_bhh0, e_bih1, e_bhh1,
        cls_W, cls_b, pprobs);

    // tags
    gemm_kernel<1><<<dim3(NN/64, TT/64), 256>>>(pGS, pWThead, head_b, nullptr, out_head, HGH, TT);
    gemm_kernel<1><<<dim3(NN/64, TT/64), 256>>>(pGS, pWTdep,  dep_b,  nullptr, out_dep,  HGH, TT);

    // arc_logits
    arc_kernel<<<dim3(SS, BB), SS>>>(pprobs, out_arc);
}

// round 6
// speedup vs baseline: 4.6893x; 1.2982x over previous
#include <cuda_runtime.h>
#include <cuda_bf16.h>
#include <math.h>
#include <stdint.h>

// Problem constants
#define BB   16
#define SS   512
#define SS0  511
#define DD   512
#define HGH  256
#define HEH  256
#define TT   128
#define MM   32
#define NN   (BB*SS)   // 8192

#define ROWS_PER_CTA 64
#define AST  132      // edge state stride (uint32 bf16x2 units)
#define BSTE 264      // edge B buffer stride (uint32 bf16x2 units)

// ---------------- device scratch ----------------
__device__ float  d_X   [NN*DD];
__device__ float  d_XW  [NN*HGH];
__device__ float  d_H0  [NN*HGH];
__device__ float  d_GS  [NN*HGH];
__device__ float  d_probs[MM*NN];

__device__ float    d_WT_ih0g[DD*HGH];
__device__ float    d_WT_ih1g[HGH*HGH];
__device__ uint32_t d_Bpk[3*128*256];    // bf16x2-packed e-weights, K-major pairs
__device__ float    d_WT_head[HGH*TT];
__device__ float    d_WT_dep [HGH*TT];

// ---------------- helpers ----------------
__device__ __forceinline__ float fast_tanh(float x) {
    float y;
    asm("tanh.approx.f32 %0, %1;" : "=f"(y) : "f"(x));
    return y;
}

__device__ __forceinline__ void mma_bf16(float c[4], const uint32_t a[4],
                                         uint32_t b0, uint32_t b1) {
    asm volatile("mma.sync.aligned.m16n8k16.row.col.f32.bf16.bf16.f32 "
        "{%0,%1,%2,%3},{%4,%5,%6,%7},{%8,%9},{%0,%1,%2,%3};"
        : "+f"(c[0]), "+f"(c[1]), "+f"(c[2]), "+f"(c[3])
        : "r"(a[0]), "r"(a[1]), "r"(a[2]), "r"(a[3]), "r"(b0), "r"(b1));
}

__device__ __forceinline__ uint32_t pack_bf16x2(float lo, float hi) {
    __nv_bfloat162 v = __floats2bfloat162_rn(lo, hi);
    return *reinterpret_cast<uint32_t*>(&v);
}

__device__ __forceinline__ uint32_t smem_u32(const void* p) {
    return (uint32_t)__cvta_generic_to_shared(p);
}

// ---------------- single fused prep kernel ----------------
// task 0: build X; 1: g_Wih0^T; 2: g_Wih1^T; 3: head^T; 4: dep^T;
// 5,6,7: pack e-weights to bf16x2 pairs
__device__ __forceinline__ void prep_transpose(const float* __restrict__ in,
                                               float* __restrict__ out,
                                               int R, int C, int bx, int tid)
{
    int tilesC = C >> 5, tilesR = R >> 5;
    if (bx >= tilesC * tilesR) return;
    int c0 = (bx % tilesC) << 5;
    int r0 = (bx / tilesC) << 5;
    __shared__ float tile[32][33];
    int x = tid & 31, y = tid >> 5;
    #pragma unroll
    for (int dy = 0; dy < 32; dy += 8)
        tile[y + dy][x] = in[(size_t)(r0 + y + dy) * C + c0 + x];
    __syncthreads();
    #pragma unroll
    for (int dy = 0; dy < 32; dy += 8)
        out[(size_t)(c0 + y + dy) * R + r0 + x] = tile[x][y + dy];
}

__global__ void __launch_bounds__(256) prep_kernel(
    const float* __restrict__ input, const float* __restrict__ sent,
    const float* __restrict__ g_Wih0, const float* __restrict__ g_Wih1,
    const float* __restrict__ head_W, const float* __restrict__ dep_W,
    const float* __restrict__ e_Whh0, const float* __restrict__ e_Wih1,
    const float* __restrict__ e_Whh1,
    float* __restrict__ X,
    float* __restrict__ WTih0g, float* __restrict__ WTih1g,
    float* __restrict__ WThead, float* __restrict__ WTdep,
    uint32_t* __restrict__ Bpk)
{
    int task = blockIdx.y;
    int bx   = blockIdx.x;
    int tid  = threadIdx.x;
    if (task == 0) {
        int idx = bx * 256 + tid;
        int n  = idx >> 7;
        int k4 = idx & 127;
        int b = n >> 9, s = n & 511;
        float4 v;
        if (s == 0) v = ((const float4*)sent)[k4];
        else        v = ((const float4*)input)[(size_t)((b*SS0 + s - 1) << 7) + k4];
        ((float4*)X)[idx] = v;
    } else if (task == 1) {
        prep_transpose(g_Wih0, WTih0g, HGH, DD, bx, tid);
    } else if (task == 2) {
        prep_transpose(g_Wih1, WTih1g, HGH, HGH, bx, tid);
    } else if (task == 3) {
        prep_transpose(head_W, WThead, TT, HGH, bx, tid);
    } else if (task == 4) {
        prep_transpose(dep_W, WTdep, TT, HGH, bx, tid);
    } else {
        // pack e-weight W (N=256 x K=256, row-major) into [k2][n] bf16x2
        if (bx >= 128) return;
        int seg = task - 5;                       // 0: Whh0, 1: Wih1, 2: Whh1
        const float* W = (seg == 0) ? e_Whh0 : (seg == 1) ? e_Wih1 : e_Whh1;
        uint32_t* outp = Bpk + seg * 128 * 256;
        int idx = bx * 256 + tid;
        int k2 = idx >> 8, n = idx & 255;
        float2 v = *(const float2*)&W[(size_t)n * 256 + (k2 << 1)];
        outp[k2 * 256 + n] = pack_bf16x2(v.x, v.y);
    }
}

// ---------------- g-RNN recurrence: 4-CTA cluster per batch ----------------
// Thread (jl = tid>>2, q = tid&3): output j = rank*64+jl, K-quarter q.
// Whh row-quarter in registers; h in smem (stride 68 per quarter, conflict-free);
// h broadcast to all 4 CTAs via st.async + mbarrier (2 alternating barriers).
__global__ void __launch_bounds__(256, 1) __cluster_dims__(4, 1, 1)
scan_g_cluster(const float* __restrict__ XW,
               const float* __restrict__ Whh,      // row-major 256x256
               float* __restrict__ Hout,
               const int* __restrict__ mask, int applyMask)
{
    __shared__ float hs[2][272];                   // [buf][q*68 + k]
    __shared__ alignas(8) unsigned long long mbar[2];

    int tid  = threadIdx.x;
    int rank = blockIdx.x & 3;
    int b    = blockIdx.x >> 2;
    int jl   = tid >> 2;
    int q    = tid & 3;
    int j    = rank * 64 + jl;

    // Whh[j][q*64 .. q*64+63] into registers
    float w[64];
    {
        const float4* ws = (const float4*)(Whh + (size_t)j * 256 + q * 64);
        #pragma unroll
        for (int i = 0; i < 16; i++) {
            float4 v = ws[i];
            w[4*i+0] = v.x; w[4*i+1] = v.y; w[4*i+2] = v.z; w[4*i+3] = v.w;
        }
    }

    // zero h buffers
    hs[0][tid] = 0.0f; hs[1][tid] = 0.0f;
    if (tid < 16) { hs[0][256 + tid] = 0.0f; hs[1][256 + tid] = 0.0f; }

    uint32_t mbar_l[2] = { smem_u32(&mbar[0]), smem_u32(&mbar[1]) };
    if (tid == 0) {
        asm volatile("mbarrier.init.shared.b64 [%0], 1;" :: "r"(mbar_l[0]));
        asm volatile("mbarrier.init.shared.b64 [%0], 1;" :: "r"(mbar_l[1]));
    }
    __syncthreads();
    asm volatile("barrier.cluster.arrive.aligned;" ::: "memory");
    asm volatile("barrier.cluster.wait.aligned;"   ::: "memory");

    // writer (q==0) precomputes remote addresses for both buffers + both barriers
    uint32_t rdata[2][4], rbar[2][4];
    if (q == 0) {
        uint32_t off = (uint32_t)(rank * 68 + jl) * 4u;
        uint32_t l0 = smem_u32(hs[0]) + off;
        uint32_t l1 = smem_u32(hs[1]) + off;
        #pragma unroll
        for (int c = 0; c < 4; c++) {
            asm("mapa.shared::cluster.u32 %0, %1, %2;" : "=r"(rdata[0][c]) : "r"(l0), "r"(c));
            asm("mapa.shared::cluster.u32 %0, %1, %2;" : "=r"(rdata[1][c]) : "r"(l1), "r"(c));
            asm("mapa.shared::cluster.u32 %0, %1, %2;" : "=r"(rbar[0][c]) : "r"(mbar_l[0]), "r"(c));
            asm("mapa.shared::cluster.u32 %0, %1, %2;" : "=r"(rbar[1][c]) : "r"(mbar_l[1]), "r"(c));
        }
    }

    float xw_cur = (q == 0) ? XW[(size_t)(b * SS) * 256 + j] : 0.0f;
    float mf_cur = 1.0f;
    int cur = 0;

    for (int t = 0; t < SS; t++) {
        // prefetch next step's xw and mask factor
        float xw_next = 0.0f, mf_next = 1.0f;
        if (q == 0 && t + 1 < SS) {
            xw_next = XW[(size_t)(b * SS + t + 1) * 256 + j];
            if (applyMask) mf_next = (float)mask[b * SS0 + t];
        }

        // partial dot: quarter q of row j
        const float4* hq = (const float4*)(hs[cur] + q * 68);
        float a0 = 0.0f, a1 = 0.0f, a2 = 0.0f, a3 = 0.0f;
        #pragma unroll
        for (int i = 0; i < 16; i++) {
            float4 h = hq[i];
            a0 = fmaf(w[4*i+0], h.x, a0);
            a1 = fmaf(w[4*i+1], h.y, a1);
            a2 = fmaf(w[4*i+2], h.z, a2);
            a3 = fmaf(w[4*i+3], h.w, a3);
        }
        float s = (a0 + a1) + (a2 + a3);
        s += __shfl_xor_sync(0xFFFFFFFFu, s, 1);
        s += __shfl_xor_sync(0xFFFFFFFFu, s, 2);

        float hn = 0.0f;
        if (q == 0) {
            hn = fast_tanh(xw_cur + s);
            Hout[(size_t)(b * SS + t) * 256 + j] = hn * mf_cur;
        }

        __syncthreads();   // all reads of hs[cur] complete before stores of this phase

        int nb = t & 1;    // barrier index for this step
        if (q == 0) {
            uint32_t hv = __float_as_uint(hn);
            #pragma unroll
            for (int c = 0; c < 4; c++) {
                asm volatile(
                    "st.async.shared::cluster.mbarrier::complete_tx::bytes.b32 [%0], %1, [%2];"
                    :: "r"(rdata[cur ^ 1][c]), "r"(hv), "r"(rbar[nb][c]) : "memory");
            }
        }
        if (tid == 0) {
            asm volatile(
                "mbarrier.arrive.expect_tx.release.cluster.shared::cta.b64 _, [%0], 1024;"
                :: "r"(mbar_l[nb]) : "memory");
        }
        // wait: barrier nb, phase parity (t>>1)&1
        {
            uint32_t par = (t >> 1) & 1;
            asm volatile(
                "{\n\t.reg .pred P;\n"
                "WAITLP_%=:\n\t"
                "mbarrier.try_wait.parity.acquire.cluster.shared::cta.b64 P, [%0], %1;\n\t"
                "@!P bra WAITLP_%=;\n\t}"
                :: "r"(mbar_l[nb]), "r"(par) : "memory");
        }

        xw_cur = xw_next;
        mf_cur = mf_next;
        cur ^= 1;
    }
}

// ---------------- generic tiled SIMT GEMM (input proj + tags) ----------------
__device__ __forceinline__ void gemm_tile_loop(const float* __restrict__ A,
                                               const float* __restrict__ B,
                                               int K, int J, int n0, int j0, int tid,
                                               float acc[4][4],
                                               float (*As)[64], float (*Bs)[64])
{
    int tx = tid & 15, ty = tid >> 4;
    for (int k0 = 0; k0 < K; k0 += 16) {
        __syncthreads();
        {
            int row = tid >> 2;
            int kb  = (tid & 3) << 2;
            float4 av = *(const float4*)&A[(size_t)(n0 + row) * K + k0 + kb];
            As[kb + 0][row] = av.x;
            As[kb + 1][row] = av.y;
            As[kb + 2][row] = av.z;
            As[kb + 3][row] = av.w;
        }
        {
            int row = tid >> 4;
            int cb  = (tid & 15) << 2;
            *(float4*)&Bs[row][cb] = *(const float4*)&B[(size_t)(k0 + row) * J + j0 + cb];
        }
        __syncthreads();
        #pragma unroll
        for (int kk = 0; kk < 16; kk++) {
            float4 a = *(const float4*)&As[kk][ty << 2];
            float4 b = *(const float4*)&Bs[kk][tx << 2];
            acc[0][0] = fmaf(a.x, b.x, acc[0][0]);
            acc[0][1] = fmaf(a.x, b.y, acc[0][1]);
            acc[0][2] = fmaf(a.x, b.z, acc[0][2]);
            acc[0][3] = fmaf(a.x, b.w, acc[0][3]);
            acc[1][0] = fmaf(a.y, b.x, acc[1][0]);
            acc[1][1] = fmaf(a.y, b.y, acc[1][1]);
            acc[1][2] = fmaf(a.y, b.z, acc[1][2]);
            acc[1][3] = fmaf(a.y, b.w, acc[1][3]);
            acc[2][0] = fmaf(a.z, b.x, acc[2][0]);
            acc[2][1] = fmaf(a.z, b.y, acc[2][1]);
            acc[2][2] = fmaf(a.z, b.z, acc[2][2]);
            acc[2][3] = fmaf(a.z, b.w, acc[2][3]);
            acc[3][0] = fmaf(a.w, b.x, acc[3][0]);
            acc[3][1] = fmaf(a.w, b.y, acc[3][1]);
            acc[3][2] = fmaf(a.w, b.z, acc[3][2]);
            acc[3][3] = fmaf(a.w, b.w, acc[3][3]);
        }
    }
}

// EPI: 0 = +b1+b2 ; 1 = elu(+b1)
template<int EPI>
__global__ void __launch_bounds__(256) gemm_kernel(const float* __restrict__ A,
                                                   const float* __restrict__ B,
                                                   const float* __restrict__ b1,
                                                   const float* __restrict__ b2,
                                                   float* __restrict__ C,
                                                   int K, int J)
{
    __shared__ float As[16][64];
    __shared__ float Bs[16][64];
    int tid = threadIdx.x;
    int n0 = blockIdx.x * 64;
    int j0 = blockIdx.y * 64;
    float acc[4][4] = {};
    gemm_tile_loop(A, B, K, J, n0, j0, tid, acc, As, Bs);

    int tx = tid & 15, ty = tid >> 4;
    int j_base = j0 + (tx << 2);
    #pragma unroll
    for (int i = 0; i < 4; i++) {
        int n = n0 + (ty << 2) + i;
        float r[4];
        #pragma unroll
        for (int l = 0; l < 4; l++) {
            int j = j_base + l;
            float x = acc[i][l];
            if (EPI == 0) {
                x += b1[j] + b2[j];
            } else {
                x += b1[j];
                x = (x > 0.0f) ? x : expm1f(x);
            }
            r[l] = x;
        }
        *(float4*)&C[(size_t)n * J + j_base] = make_float4(r[0], r[1], r[2], r[3]);
    }
}

// ---------------- fused edge scan: bf16 MMA, cp.async 3-buffer pipeline ----------
__device__ __forceinline__ void edge_cp_chunk(uint32_t* Bs, int nb,
                                              const uint32_t* src, int tid)
{
    uint32_t dstb = (uint32_t)__cvta_generic_to_shared(Bs + nb * 32 * BSTE);
    #pragma unroll
    for (int i = 0; i < 8; i++) {
        int f = tid + (i << 8);
        int r = f >> 6, c4 = f & 63;
        uint32_t d = dstb + (uint32_t)(r * BSTE + (c4 << 2)) * 4u;
        asm volatile("cp.async.cg.shared.global [%0], [%1], 16;"
                     :: "r"(d), "l"(src + r * 256 + (c4 << 2)));
    }
    asm volatile("cp.async.commit_group;");
}

__device__ __forceinline__ void edge_pass(
    const uint32_t* __restrict__ hA0, const uint32_t* __restrict__ Bg0, int n0ch,
    const uint32_t* __restrict__ hA1, const uint32_t* __restrict__ Bg1, int n1ch,
    uint32_t* __restrict__ Bs, float acc[2][8][4],
    int rg, int cg, int gid, int tig, int tid)
{
    int nch = n0ch + n1ch;
    edge_cp_chunk(Bs, 0, (0 < n0ch) ? Bg0 : Bg1, tid);
    edge_cp_chunk(Bs, 1, (1 < n0ch) ? (Bg0 + 32*256) : (Bg1 + (1 - n0ch) * 32*256), tid);

    for (int c = 0; c < nch; c++) {
        if (c + 1 < nch) asm volatile("cp.async.wait_group 1;");
        else             asm volatile("cp.async.wait_group 0;");
        __syncthreads();

        const uint32_t* hA = (c < n0ch) ? hA0 : hA1;
        int aBase = ((c < n0ch) ? c : (c - n0ch)) * 32;
        const uint32_t* Bb = Bs + (c % 3) * 32 * BSTE;

        #pragma unroll
        for (int ks = 0; ks < 4; ks++) {
            uint32_t a[2][4];
            #pragma unroll
            for (int mt = 0; mt < 2; mt++) {
                int r0 = rg*32 + mt*16 + gid;
                int kb = aBase + ks*8 + tig;
                a[mt][0] = hA[r0*AST + kb];
                a[mt][1] = hA[(r0+8)*AST + kb];
                a[mt][2] = hA[r0*AST + kb + 4];
                a[mt][3] = hA[(r0+8)*AST + kb + 4];
            }
            #pragma unroll
            for (int nt = 0; nt < 8; nt++) {
                int col = cg*64 + nt*8 + gid;
                uint32_t b0 = Bb[(ks*8 + tig)*BSTE + col];
                uint32_t b1 = Bb[(ks*8 + tig + 4)*BSTE + col];
                mma_bf16(acc[0][nt], a[0], b0, b1);
                mma_bf16(acc[1][nt], a[1], b0, b1);
            }
        }
        int cn = c + 2;
        if (cn < nch) {
            const uint32_t* s = (cn < n0ch) ? (Bg0 + cn * 32*256)
                                            : (Bg1 + (cn - n0ch) * 32*256);
            edge_cp_chunk(Bs, cn % 3, s, tid);
        }
    }
}

__global__ void __launch_bounds__(256, 1) edge_fused_kernel(
    const float* __restrict__ gs,
    const uint32_t* __restrict__ Bpk,       // [3][128*256]
    const float* __restrict__ w0,
    const float* __restrict__ bih0, const float* __restrict__ bhh0,
    const float* __restrict__ bih1, const float* __restrict__ bhh1,
    const float* __restrict__ clsW, const float* __restrict__ clsb,
    float* __restrict__ probs)
{
    extern __shared__ uint32_t smu[];
    uint32_t* hs0 = smu;
    uint32_t* hs1 = hs0 + ROWS_PER_CTA*AST;
    uint32_t* Bs  = hs1 + ROWS_PER_CTA*AST;
    float* fsm = (float*)(Bs + 3*32*BSTE);
    float* ps  = fsm;
    float* w0s = ps + 64;
    float* bc0 = w0s + 256;
    float* bc1 = bc0 + 256;
    float* clw = bc1 + 256;
    __shared__ float s_clsb;

    int tid = threadIdx.x;
    int lane = tid & 31, warp = tid >> 5;
    int gid = lane >> 2, tig = lane & 3;
    int rg = warp >> 2, cg = warp & 3;
    int n0 = blockIdx.x * ROWS_PER_CTA;

    const uint32_t* B0 = Bpk;
    const uint32_t* B1 = Bpk + 128*256;
    const uint32_t* B2 = Bpk + 2*128*256;

    w0s[tid] = w0[tid];
    bc0[tid] = bih0[tid] + bhh0[tid];
    bc1[tid] = bih1[tid] + bhh1[tid];
    clw[tid] = clsW[tid];
    if (tid == 0) s_clsb = clsb[0];

    for (int i = tid; i < ROWS_PER_CTA*128; i += 256) {
        int r = i >> 7, c2 = i & 127;
        float2 v = *(const float2*)&gs[(size_t)(n0 + r)*256 + (c2 << 1)];
        hs0[r*AST + c2] = pack_bf16x2(v.x, v.y);
        hs1[r*AST + c2] = 0u;
    }
    if (tid < ROWS_PER_CTA) ps[tid] = 1.0f;
    __syncthreads();

    float acc[2][8][4];

    for (int m = 0; m < MM; m++) {
        #pragma unroll
        for (int mt = 0; mt < 2; mt++)
            #pragma unroll
            for (int nt = 0; nt < 8; nt++)
                #pragma unroll
                for (int q = 0; q < 4; q++) acc[mt][nt][q] = 0.0f;

        edge_pass(hs0, B0, 4, hs0, B0, 0, Bs, acc, rg, cg, gid, tig, tid);
        __syncthreads();

        #pragma unroll
        for (int mt = 0; mt < 2; mt++) {
            int r0 = rg*32 + mt*16 + gid;
            int r1 = r0 + 8;
            float p0 = ps[r0], p1 = ps[r1];
            #pragma unroll
            for (int nt = 0; nt < 8; nt++) {
                int cbase = cg*64 + nt*8 + tig*2;
                float x0 = acc[mt][nt][0] + p0*w0s[cbase]   + bc0[cbase];
                float x1 = acc[mt][nt][1] + p0*w0s[cbase+1] + bc0[cbase+1];
                float x2 = acc[mt][nt][2] + p1*w0s[cbase]   + bc0[cbase];
                float x3 = acc[mt][nt][3] + p1*w0s[cbase+1] + bc0[cbase+1];
                hs0[r0*AST + (cbase >> 1)] = pack_bf16x2(fast_tanh(x0), fast_tanh(x1));
                hs0[r1*AST + (cbase >> 1)] = pack_bf16x2(fast_tanh(x2), fast_tanh(x3));
            }
        }
        __syncthreads();

        #pragma unroll
        for (int mt = 0; mt < 2; mt++)
            #pragma unroll
            for (int nt = 0; nt < 8; nt++)
                #pragma unroll
                for (int q = 0; q < 4; q++) acc[mt][nt][q] = 0.0f;

        edge_pass(hs0, B1, 4, hs1, B2, 4, Bs, acc, rg, cg, gid, tig, tid);
        __syncthreads();

        #pragma unroll
        for (int mt = 0; mt < 2; mt++) {
            int r0 = rg*32 + mt*16 + gid;
            int r1 = r0 + 8;
            #pragma unroll
            for (int nt = 0; nt < 8; nt++) {
                int cbase = cg*64 + nt*8 + tig*2;
                float x0 = acc[mt][nt][0] + bc1[cbase];
                float x1 = acc[mt][nt][1] + bc1[cbase+1];
                float x2 = acc[mt][nt][2] + bc1[cbase];
                float x3 = acc[mt][nt][3] + bc1[cbase+1];
                hs1[r0*AST + (cbase >> 1)] = pack_bf16x2(fast_tanh(x0), fast_tanh(x1));
                hs1[r1*AST + (cbase >> 1)] = pack_bf16x2(fast_tanh(x2), fast_tanh(x3));
            }
        }
        __syncthreads();

        #pragma unroll
        for (int i = 0; i < 8; i++) {
            int r = warp*8 + i;
            float s = 0.0f;
            #pragma unroll
            for (int k = 0; k < 4; k++) {
                int c2 = lane + k*32;
                __nv_bfloat162 bv = *reinterpret_cast<const __nv_bfloat162*>(&hs1[r*AST + c2]);
                float2 fv = __bfloat1622float2(bv);
                s = fmaf(fv.x, clw[c2*2], fmaf(fv.y, clw[c2*2 + 1], s));
            }
            #pragma unroll
            for (int o = 16; o; o >>= 1) s += __shfl_xor_sync(0xFFFFFFFFu, s, o);
            if (lane == 0) {
                float p = 1.0f / (1.0f + expf(-(s + s_clsb)));
                ps[r] = p;
                probs[(size_t)m*NN + n0 + r] = p;
            }
        }
        __syncthreads();
    }
}

// ---------------- arc_logits assembly ----------------
__global__ void arc_kernel(const float* __restrict__ probs, float* __restrict__ arc)
{
    int j = blockIdx.x;
    int b = blockIdx.y;
    int i = threadIdx.x;
    int start = (i - MM > 0) ? (i - MM) : 0;
    float v = 0.0f;
    if (j >= start && j < i) {
        int midx = j - start;
        v = probs[(size_t)midx * NN + b * SS + i];
    }
    arc[(size_t)(b * SS + j) * SS + i] = v;
}

// ---------------- host orchestration ----------------
static const int EDGE_SMEM_BYTES =
    (2*ROWS_PER_CTA*AST + 3*32*BSTE) * 4 + (64 + 4*256) * 4;

extern "C" void kernel_launch(void* const* d_in, const int* in_sizes, int n_in,
                              void* d_out, int out_size)
{
    const float* input   = (const float*)d_in[0];
    const float* sentinel= (const float*)d_in[1];
    const float* g_Wih0  = (const float*)d_in[2];
    const float* g_Whh0  = (const float*)d_in[3];
    const float* g_bih0  = (const float*)d_in[4];
    const float* g_bhh0  = (const float*)d_in[5];
    const float* g_Wih1  = (const float*)d_in[6];
    const float* g_Whh1  = (const float*)d_in[7];
    const float* g_bih1  = (const float*)d_in[8];
    const float* g_bhh1  = (const float*)d_in[9];
    const float* e_Wih0  = (const float*)d_in[10];
    const float* e_Whh0  = (const float*)d_in[11];
    const float* e_bih0  = (const float*)d_in[12];
    const float* e_bhh0  = (const float*)d_in[13];
    const float* e_Wih1  = (const float*)d_in[14];
    const float* e_Whh1  = (const float*)d_in[15];
    const float* e_bih1  = (const float*)d_in[16];
    const float* e_bhh1  = (const float*)d_in[17];
    const float* cls_W   = (const float*)d_in[18];
    const float* cls_b   = (const float*)d_in[19];
    const float* head_W  = (const float*)d_in[20];
    const float* head_b  = (const float*)d_in[21];
    const float* dep_W   = (const float*)d_in[22];
    const float* dep_b   = (const float*)d_in[23];
    const int*   mask    = (const int*)  d_in[24];
    (void)in_sizes; (void)n_in; (void)out_size;

    float* out = (float*)d_out;
    float* out_head = out;
    float* out_dep  = out + (size_t)NN * TT;
    float* out_arc  = out + (size_t)2 * NN * TT;

    float *pX, *pXW, *pH0, *pGS, *pprobs;
    float *pWTih0g, *pWTih1g, *pWThead, *pWTdep;
    uint32_t *pBpk;
    cudaGetSymbolAddress((void**)&pX, d_X);
    cudaGetSymbolAddress((void**)&pXW, d_XW);
    cudaGetSymbolAddress((void**)&pH0, d_H0);
    cudaGetSymbolAddress((void**)&pGS, d_GS);
    cudaGetSymbolAddress((void**)&pprobs, d_probs);
    cudaGetSymbolAddress((void**)&pWTih0g, d_WT_ih0g);
    cudaGetSymbolAddress((void**)&pWTih1g, d_WT_ih1g);
    cudaGetSymbolAddress((void**)&pWThead, d_WT_head);
    cudaGetSymbolAddress((void**)&pWTdep, d_WT_dep);
    cudaGetSymbolAddress((void**)&pBpk, d_Bpk);

    cudaFuncSetAttribute(edge_fused_kernel,
                         cudaFuncAttributeMaxDynamicSharedMemorySize, EDGE_SMEM_BYTES);

    // launch 1: fused prep
    prep_kernel<<<dim3(4096, 8), 256>>>(
        input, sentinel, g_Wih0, g_Wih1, head_W, dep_W,
        e_Whh0, e_Wih1, e_Whh1,
        pX, pWTih0g, pWTih1g, pWThead, pWTdep, pBpk);

    // launches 2-5: g-RNN layers (cluster scan, W in registers)
    gemm_kernel<0><<<dim3(NN/64, HGH/64), 256>>>(pX, pWTih0g, g_bih0, g_bhh0, pXW, DD, HGH);
    scan_g_cluster<<<BB*4, 256>>>(pXW, g_Whh0, pH0, nullptr, 0);
    gemm_kernel<0><<<dim3(NN/64, HGH/64), 256>>>(pH0, pWTih1g, g_bih1, g_bhh1, pXW, HGH, HGH);
    scan_g_cluster<<<BB*4, 256>>>(pXW, g_Whh1, pGS, mask, 1);

    // launch 6: fused edge scan (bf16 tensor cores)
    edge_fused_kernel<<<NN/ROWS_PER_CTA, 256, EDGE_SMEM_BYTES>>>(
        pGS, pBpk, e_Wih0, e_bih0, e_bhh0, e_bih1, e_bhh1,
        cls_W, cls_b, pprobs);

    // tags
    gemm_kernel<1><<<dim3(NN/64, TT/64), 256>>>(pGS, pWThead, head_b, nullptr, out_head, HGH, TT);
    gemm_kernel<1><<<dim3(NN/64, TT/64), 256>>>(pGS, pWTdep,  dep_b,  nullptr, out_dep,  HGH, TT);

    // arc_logits
    arc_kernel<<<dim3(SS, BB), SS>>>(pprobs, out_arc);
}